// round 1
// baseline (speedup 1.0000x reference)
#include <cuda_runtime.h>

#define BB 8
#define TT 2048
#define CC 1024
#define HH 64
#define SCALE 0.125f

// Scratch (device globals: no allocation in kernel_launch allowed)
__device__ float g_aff[(size_t)BB * TT * TT];   // 128 MB, lower triangle valid
__device__ float g_q[BB * TT * HH];
__device__ float g_k[BB * TT * HH];
__device__ float g_v[BB * TT * HH];
__device__ float g_c[BB * TT];                  // per-column m + log(Z)

// ---------------------------------------------------------------------------
// Kernel 1: q/k/v = x @ W^T.  M=B*T=16384, K=C=1024, N=H=64.
// Grid: (M/64, 3). Block 256. 64x64 output tile, 4x4 micro-tile per thread.
// ---------------------------------------------------------------------------
__global__ __launch_bounds__(256) void qkv_kernel(const float* __restrict__ x,
                                                  const float* __restrict__ Wq,
                                                  const float* __restrict__ Wk,
                                                  const float* __restrict__ Wv) {
    __shared__ float xs[64][65];   // xs[m_local][kk]
    __shared__ float ws[64][65];   // ws[kk][h]
    const float* W  = blockIdx.y == 0 ? Wq : (blockIdx.y == 1 ? Wk : Wv);
    float* out      = blockIdx.y == 0 ? g_q : (blockIdx.y == 1 ? g_k : g_v);
    const int tid = threadIdx.x;
    const int tx = tid & 15, ty = tid >> 4;
    const int m0 = blockIdx.x * 64;

    float acc[4][4] = {};
    for (int c0 = 0; c0 < CC; c0 += 64) {
        #pragma unroll
        for (int i = tid; i < 4096; i += 256) {
            int r = i >> 6, cc = i & 63;
            xs[r][cc] = x[(size_t)(m0 + r) * CC + c0 + cc];  // coalesced
            ws[cc][r] = W[r * CC + c0 + cc];                 // transpose-in-smem
        }
        __syncthreads();
        #pragma unroll 8
        for (int kk = 0; kk < 64; kk++) {
            float a[4], b[4];
            #pragma unroll
            for (int i = 0; i < 4; i++) a[i] = xs[ty * 4 + i][kk];
            #pragma unroll
            for (int j = 0; j < 4; j++) b[j] = ws[kk][tx * 4 + j];
            #pragma unroll
            for (int i = 0; i < 4; i++)
                #pragma unroll
                for (int j = 0; j < 4; j++)
                    acc[i][j] += a[i] * b[j];
        }
        __syncthreads();
    }
    #pragma unroll
    for (int i = 0; i < 4; i++)
        #pragma unroll
        for (int j = 0; j < 4; j++)
            out[(size_t)(m0 + ty * 4 + i) * HH + tx * 4 + j] = acc[i][j];
}

// ---------------------------------------------------------------------------
// Kernel 2: aff[b,t,s] = (q[b,t,:] . k[b,s,:]) * SCALE  for s <= t.
// Grid: (T/64 s-tiles, T/64 t-tiles, B). Blocks fully above diagonal exit.
// ---------------------------------------------------------------------------
__global__ __launch_bounds__(256) void aff_kernel() {
    const int b  = blockIdx.z;
    const int s0 = blockIdx.x * 64;
    const int t0 = blockIdx.y * 64;
    if (s0 > t0 + 63) return;   // whole tile has s > t

    __shared__ float qs[64][65];   // qs[t_local][h]
    __shared__ float kt[64][65];   // kt[h][s_local]
    const int tid = threadIdx.x;
    const int tx = tid & 15, ty = tid >> 4;
    const float* qb = g_q + (size_t)b * TT * HH;
    const float* kb = g_k + (size_t)b * TT * HH;

    #pragma unroll
    for (int i = tid; i < 4096; i += 256) {
        int r = i >> 6, cc = i & 63;
        qs[r][cc] = qb[(size_t)(t0 + r) * HH + cc];
        kt[cc][r] = kb[(size_t)(s0 + r) * HH + cc];
    }
    __syncthreads();

    float acc[4][4] = {};
    #pragma unroll 8
    for (int kk = 0; kk < 64; kk++) {
        float a[4], c[4];
        #pragma unroll
        for (int i = 0; i < 4; i++) a[i] = qs[ty * 4 + i][kk];
        #pragma unroll
        for (int j = 0; j < 4; j++) c[j] = kt[kk][tx * 4 + j];
        #pragma unroll
        for (int i = 0; i < 4; i++)
            #pragma unroll
            for (int j = 0; j < 4; j++)
                acc[i][j] += a[i] * c[j];
    }

    float* affb = g_aff + (size_t)b * TT * TT;
    #pragma unroll
    for (int i = 0; i < 4; i++)
        #pragma unroll
        for (int j = 0; j < 4; j++) {
            int t = t0 + ty * 4 + i;
            int s = s0 + tx * 4 + j;
            if (s <= t) affb[(size_t)t * TT + s] = acc[i][j] * SCALE;
        }
}

// ---------------------------------------------------------------------------
// Kernel 3: per-COLUMN softmax stats (softmax over axis=1 / query axis!).
// For column s: m_s = max_{t>=s} aff[t,s], Z_s = sum exp(aff-m).
// Stores c_s = m_s + log(Z_s) so consumer computes exp(aff - c_s) directly.
// Grid: (T/64, B), block 256 = 64 columns x 4 row-lanes (coalesced row reads).
// ---------------------------------------------------------------------------
__global__ __launch_bounds__(256) void colstat_kernel() {
    const int b  = blockIdx.y;
    const int s0 = blockIdx.x * 64;
    const int tid = threadIdx.x;
    const int sl = tid & 63, tr = tid >> 6;
    const int s = s0 + sl;
    const float* affb = g_aff + (size_t)b * TT * TT;

    float m = -1e30f, z = 0.f;
    for (int t = s0 + tr; t < TT; t += 4) {
        if (t >= s) {  // only lower triangle was written
            float a = affb[(size_t)t * TT + s];
            if (a > m) { z = z * __expf(m - a) + 1.f; m = a; }
            else        { z += __expf(a - m); }
        }
    }
    __shared__ float sm[4][64], sz[4][64];
    sm[tr][sl] = m; sz[tr][sl] = z;
    __syncthreads();
    if (tr == 0) {
        float M = fmaxf(fmaxf(sm[0][sl], sm[1][sl]), fmaxf(sm[2][sl], sm[3][sl]));
        float Z = 0.f;
        #pragma unroll
        for (int r = 0; r < 4; r++) Z += sz[r][sl] * __expf(sm[r][sl] - M);
        g_c[b * TT + s] = M + __logf(Z);
    }
}

// ---------------------------------------------------------------------------
// Kernel 4: out[b,t,h] = sum_{s<=t} exp(aff[t,s] - c_s) * v[b,s,h].
// Grid: (T/64 t-tiles, B). Loops s-tiles 0..t0. exp fused into smem load.
// ---------------------------------------------------------------------------
__global__ __launch_bounds__(256) void out_kernel(float* __restrict__ outp) {
    const int b  = blockIdx.y;
    const int t0 = blockIdx.x * 64;
    const int tid = threadIdx.x;
    const int tx = tid & 15, ty = tid >> 4;

    __shared__ float ps[64][65];   // exp-transformed aff tile [t][s]
    __shared__ float vs[64][65];   // vs[s_local][h]
    __shared__ float csh[TT];      // per-column c = m + logZ (range used: [0, t0+64))

    const float* cb   = g_c + b * TT;
    const float* affb = g_aff + (size_t)b * TT * TT;
    const float* vb   = g_v + (size_t)b * TT * HH;

    for (int i = tid; i < t0 + 64; i += 256) csh[i] = cb[i];
    __syncthreads();

    float acc[4][4] = {};
    for (int s0 = 0; s0 <= t0; s0 += 64) {
        #pragma unroll
        for (int i = tid; i < 4096; i += 256) {
            int r = i >> 6, cc = i & 63;
            int t = t0 + r, s = s0 + cc;
            ps[r][cc] = (s <= t) ? __expf(affb[(size_t)t * TT + s] - csh[s]) : 0.f;
            vs[r][cc] = vb[(size_t)(s0 + r) * HH + cc];
        }
        __syncthreads();
        #pragma unroll 8
        for (int kk = 0; kk < 64; kk++) {
            float a[4], c[4];
            #pragma unroll
            for (int i = 0; i < 4; i++) a[i] = ps[ty * 4 + i][kk];
            #pragma unroll
            for (int j = 0; j < 4; j++) c[j] = vs[kk][tx * 4 + j];
            #pragma unroll
            for (int i = 0; i < 4; i++)
                #pragma unroll
                for (int j = 0; j < 4; j++)
                    acc[i][j] += a[i] * c[j];
        }
        __syncthreads();
    }
    #pragma unroll
    for (int i = 0; i < 4; i++)
        #pragma unroll
        for (int j = 0; j < 4; j++)
            outp[((size_t)b * TT + t0 + ty * 4 + i) * HH + tx * 4 + j] = acc[i][j];
}

// ---------------------------------------------------------------------------
extern "C" void kernel_launch(void* const* d_in, const int* in_sizes, int n_in,
                              void* d_out, int out_size) {
    const float* x  = (const float*)d_in[0];
    const float* Wq = (const float*)d_in[1];
    const float* Wk = (const float*)d_in[2];
    const float* Wv = (const float*)d_in[3];
    float* out = (float*)d_out;

    qkv_kernel<<<dim3((BB * TT) / 64, 3), 256>>>(x, Wq, Wk, Wv);
    aff_kernel<<<dim3(TT / 64, TT / 64, BB), 256>>>();
    colstat_kernel<<<dim3(TT / 64, BB), 256>>>();
    out_kernel<<<dim3(TT / 64, BB), 256>>>(out);
}

// round 3
// speedup vs baseline: 1.6797x; 1.6797x over previous
#include <cuda_runtime.h>

#define BB 8
#define TT 2048
#define CC 1024
#define HH 64
#define SCALE 0.125f

// ---------------------------------------------------------------------------
// Scratch (device globals; no allocations allowed)
// ---------------------------------------------------------------------------
__device__ float g_ET[(size_t)BB * TT * TT];  // E^T[s][t] = exp(aff[t][s]), 128MB
__device__ float g_qT[(size_t)BB * HH * TT];  // q transposed [b][h][t]
__device__ float g_kT[(size_t)BB * HH * TT];  // k transposed [b][h][s]
__device__ float g_v [(size_t)BB * TT * HH];  // v row-major  [b][s][h]
__device__ float g_vs[(size_t)BB * TT * HH];  // v / Z_s      [b][s][h]

// ---------------------------------------------------------------------------
// Kernel 1: q/k/v projections.  M = B*T = 16384, K = C = 1024, N = H = 64.
// BM=128, Kc=32, 128 threads, 8x8 microtile (16 row-thr x 8 col-thr).
// blockIdx.y: 0 -> qT (transposed out), 1 -> kT (transposed), 2 -> v (row-major).
// ---------------------------------------------------------------------------
__global__ __launch_bounds__(128) void qkv_kernel(const float* __restrict__ x,
                                                  const float* __restrict__ Wq,
                                                  const float* __restrict__ Wk,
                                                  const float* __restrict__ Wv) {
    __shared__ float smem[64 * 132];          // 33.8KB (transpose buf is max user)
    float* xs = smem;                         // [32][132]  x^T chunk: xs[c][m]
    float* ws = smem + 32 * 132;              // [32][68]   W^T chunk: ws[c][h]

    const int which = blockIdx.y;
    const float* W = (which == 0) ? Wq : (which == 1) ? Wk : Wv;
    const int m0  = blockIdx.x * 128;
    const int tid = threadIdx.x;
    const int tx  = tid & 7;                  // h-col group (8 cols)
    const int tyr = tid >> 3;                 // m-row group (16 rows of 8)

    float acc[8][8] = {};

    for (int c0 = 0; c0 < CC; c0 += 32) {
        // x tile 128x32 -> xs[c][m]  (1024 float4, 8/thread)
        #pragma unroll
        for (int it = 0; it < 8; it++) {
            int i = tid + it * 128;
            int m = i >> 3, cg = i & 7;
            float4 xv = *(const float4*)&x[(size_t)(m0 + m) * CC + c0 + cg * 4];
            xs[(cg * 4 + 0) * 132 + m] = xv.x;
            xs[(cg * 4 + 1) * 132 + m] = xv.y;
            xs[(cg * 4 + 2) * 132 + m] = xv.z;
            xs[(cg * 4 + 3) * 132 + m] = xv.w;
        }
        // W tile 64x32 -> ws[c][h]  (512 float4, 4/thread)
        #pragma unroll
        for (int it = 0; it < 4; it++) {
            int i = tid + it * 128;
            int h = i >> 3, cg = i & 7;
            float4 wv = *(const float4*)&W[(size_t)h * CC + c0 + cg * 4];
            ws[(cg * 4 + 0) * 68 + h] = wv.x;
            ws[(cg * 4 + 1) * 68 + h] = wv.y;
            ws[(cg * 4 + 2) * 68 + h] = wv.z;
            ws[(cg * 4 + 3) * 68 + h] = wv.w;
        }
        __syncthreads();

        #pragma unroll 4
        for (int kk = 0; kk < 32; kk++) {
            float4 a0 = *(const float4*)&xs[kk * 132 + tyr * 8];
            float4 a1 = *(const float4*)&xs[kk * 132 + tyr * 8 + 4];
            float4 b0 = *(const float4*)&ws[kk * 68 + tx * 8];
            float4 b1 = *(const float4*)&ws[kk * 68 + tx * 8 + 4];
            float a[8] = {a0.x, a0.y, a0.z, a0.w, a1.x, a1.y, a1.z, a1.w};
            float b[8] = {b0.x, b0.y, b0.z, b0.w, b1.x, b1.y, b1.z, b1.w};
            #pragma unroll
            for (int i = 0; i < 8; i++)
                #pragma unroll
                for (int j = 0; j < 8; j++)
                    acc[i][j] += a[i] * b[j];
        }
        __syncthreads();
    }

    if (which == 2) {
        // v row-major [M][64]
        #pragma unroll
        for (int i = 0; i < 8; i++) {
            float4 v0 = make_float4(acc[i][0], acc[i][1], acc[i][2], acc[i][3]);
            float4 v1 = make_float4(acc[i][4], acc[i][5], acc[i][6], acc[i][7]);
            float* p = &g_v[(size_t)(m0 + tyr * 8 + i) * HH + tx * 8];
            *(float4*)p = v0;
            *(float4*)(p + 4) = v1;
        }
    } else {
        // transpose 128x64 tile through smem -> [b][h][t]
        float* trans = smem;                  // [64][132]
        #pragma unroll
        for (int i = 0; i < 8; i++)
            #pragma unroll
            for (int j = 0; j < 8; j++)
                trans[(tx * 8 + j) * 132 + tyr * 8 + i] = acc[i][j];
        __syncthreads();
        float* dst = (which == 0) ? g_qT : g_kT;
        const int b    = m0 >> 11;            // TT = 2048
        const int tloc = m0 & (TT - 1);
        #pragma unroll
        for (int it = 0; it < 16; it++) {
            int i = tid + it * 128;           // 0..2047
            int h = i >> 5, m4 = i & 31;
            float4 tv = *(const float4*)&trans[h * 132 + m4 * 4];
            *(float4*)&dst[((size_t)b * HH + h) * TT + tloc + m4 * 4] = tv;
        }
    }
}

// ---------------------------------------------------------------------------
// Kernel 2: E^T[s][t] = (s<=t) ? exp((q_t . k_s) * SCALE) : 0
// 128x128 tiles, K=64 in 2 chunks of 32. 256 threads, 8x8 microtile.
// Grid (t_tile=16, s_tile=16, B); upper-tri tiles exit.
// ---------------------------------------------------------------------------
__global__ __launch_bounds__(256) void aff_kernel() {
    const int ttile = blockIdx.x, stile = blockIdx.y, b = blockIdx.z;
    if (stile > ttile) return;
    const int t0 = ttile * 128, s0 = stile * 128;

    __shared__ float qs[32 * 132];            // qs[h][t]
    __shared__ float ks[32 * 132];            // ks[h][s]
    const float* qT = g_qT + (size_t)b * HH * TT;
    const float* kT = g_kT + (size_t)b * HH * TT;

    const int tid = threadIdx.x;
    const int tx = tid & 15;                  // s cols (16 x 8)
    const int ty = tid >> 4;                  // t rows (16 x 8)

    float acc[8][8] = {};                     // acc[t_i][s_j]

    for (int c0 = 0; c0 < HH; c0 += 32) {
        #pragma unroll
        for (int it = 0; it < 4; it++) {
            int i = tid + it * 256;           // 0..1023
            int r = i >> 5, m4 = i & 31;
            *(float4*)&qs[r * 132 + m4 * 4] =
                *(const float4*)&qT[(size_t)(c0 + r) * TT + t0 + m4 * 4];
            *(float4*)&ks[r * 132 + m4 * 4] =
                *(const float4*)&kT[(size_t)(c0 + r) * TT + s0 + m4 * 4];
        }
        __syncthreads();

        #pragma unroll 4
        for (int kk = 0; kk < 32; kk++) {
            float4 a0 = *(const float4*)&qs[kk * 132 + ty * 8];
            float4 a1 = *(const float4*)&qs[kk * 132 + ty * 8 + 4];
            float4 b0 = *(const float4*)&ks[kk * 132 + tx * 8];
            float4 b1 = *(const float4*)&ks[kk * 132 + tx * 8 + 4];
            float a[8] = {a0.x, a0.y, a0.z, a0.w, a1.x, a1.y, a1.z, a1.w};
            float bb[8] = {b0.x, b0.y, b0.z, b0.w, b1.x, b1.y, b1.z, b1.w};
            #pragma unroll
            for (int i = 0; i < 8; i++)
                #pragma unroll
                for (int j = 0; j < 8; j++)
                    acc[i][j] += a[i] * bb[j];
        }
        __syncthreads();
    }

    // epilogue: exp + causal mask, store E^T[s][t]
    float* ET = g_ET + (size_t)b * TT * TT;
    #pragma unroll
    for (int j = 0; j < 8; j++) {
        const int s = s0 + tx * 8 + j;
        float e[8];
        #pragma unroll
        for (int i = 0; i < 8; i++) {
            const int t = t0 + ty * 8 + i;
            e[i] = (s <= t) ? __expf(acc[i][j] * SCALE) : 0.0f;
        }
        float* p = &ET[(size_t)s * TT + t0 + ty * 8];
        *(float4*)p       = make_float4(e[0], e[1], e[2], e[3]);
        *(float4*)(p + 4) = make_float4(e[4], e[5], e[6], e[7]);
    }
}

// ---------------------------------------------------------------------------
// Kernel 3: Z_s = sum_t E^T[s][t] (row sum, coalesced), then v'[s] = v[s]/Z_s.
// Grid (T/32, B); 256 thr = 32 rows x 8 lanes.
// ---------------------------------------------------------------------------
__global__ __launch_bounds__(256) void colsum_kernel() {
    const int b = blockIdx.y;
    const int s0 = blockIdx.x * 32;
    const int tid = threadIdx.x;
    const int row = tid >> 3, l8 = tid & 7;
    const int s = s0 + row;
    const float* ET = g_ET + (size_t)b * TT * TT;

    const int tb = (s >> 7) << 7;             // first written (tile-aligned) col
    float4 a = make_float4(0.f, 0.f, 0.f, 0.f);
    for (int t = tb + l8 * 4; t < TT; t += 32) {
        float4 ev = *(const float4*)&ET[(size_t)s * TT + t];
        a.x += ev.x; a.y += ev.y; a.z += ev.z; a.w += ev.w;
    }
    float sum = (a.x + a.y) + (a.z + a.w);
    sum += __shfl_xor_sync(0xffffffff, sum, 1);
    sum += __shfl_xor_sync(0xffffffff, sum, 2);
    sum += __shfl_xor_sync(0xffffffff, sum, 4);

    __shared__ float zr[32];
    if (l8 == 0) zr[row] = 1.0f / sum;
    __syncthreads();

    const float* v = g_v + (size_t)b * TT * HH;
    float* vs = g_vs + (size_t)b * TT * HH;
    #pragma unroll
    for (int it = 0; it < 2; it++) {
        int i = tid + it * 256;               // 0..511
        int r = i >> 4, h4 = i & 15;
        float4 vv = *(const float4*)&v[(size_t)(s0 + r) * HH + h4 * 4];
        float sc = zr[r];
        vv.x *= sc; vv.y *= sc; vv.z *= sc; vv.w *= sc;
        *(float4*)&vs[(size_t)(s0 + r) * HH + h4 * 4] = vv;
    }
}

// ---------------------------------------------------------------------------
// Kernel 4: out[t][h] = sum_s E^T[s][t] * v'[s][h].  Pure GEMM.
// BM=128(t), BN=64(h), Kc=32(s). 128 thr, 8x8 microtile. 2-way split-K over
// interleaved chunks + atomicAdd (exactly 2 commutative adds/elem -> determ.)
// ---------------------------------------------------------------------------
__global__ __launch_bounds__(128) void out_kernel(float* __restrict__ outp) {
    const int t0 = blockIdx.x * 128;
    const int split = blockIdx.y;             // 0 or 1
    const int b = blockIdx.z;
    const int nch = (t0 >> 5) + 4;            // s-chunks needed: s0 <= t0+96

    __shared__ float es[32 * 132];            // es[s][t]
    __shared__ float vs[32 * 68];             // vs[s][h]
    const float* ET  = g_ET + (size_t)b * TT * TT;
    const float* vsg = g_vs + (size_t)b * TT * HH;

    const int tid = threadIdx.x;
    const int tx = tid & 7;                   // h cols (8 x 8)
    const int tyr = tid >> 3;                 // t rows (16 x 8)

    float acc[8][8] = {};

    for (int c = split; c < nch; c += 2) {
        const int s0 = c * 32;
        #pragma unroll
        for (int it = 0; it < 8; it++) {
            int i = tid + it * 128;           // 0..1023
            int r = i >> 5, m4 = i & 31;
            *(float4*)&es[r * 132 + m4 * 4] =
                *(const float4*)&ET[(size_t)(s0 + r) * TT + t0 + m4 * 4];
        }
        #pragma unroll
        for (int it = 0; it < 4; it++) {
            int i = tid + it * 128;           // 0..511
            int r = i >> 4, h4 = i & 15;
            *(float4*)&vs[r * 68 + h4 * 4] =
                *(const float4*)&vsg[(size_t)(s0 + r) * HH + h4 * 4];
        }
        __syncthreads();

        #pragma unroll 4
        for (int kk = 0; kk < 32; kk++) {
            float4 a0 = *(const float4*)&es[kk * 132 + tyr * 8];
            float4 a1 = *(const float4*)&es[kk * 132 + tyr * 8 + 4];
            float4 b0 = *(const float4*)&vs[kk * 68 + tx * 8];
            float4 b1 = *(const float4*)&vs[kk * 68 + tx * 8 + 4];
            float a[8] = {a0.x, a0.y, a0.z, a0.w, a1.x, a1.y, a1.z, a1.w};
            float bb[8] = {b0.x, b0.y, b0.z, b0.w, b1.x, b1.y, b1.z, b1.w};
            #pragma unroll
            for (int i = 0; i < 8; i++)
                #pragma unroll
                for (int j = 0; j < 8; j++)
                    acc[i][j] += a[i] * bb[j];
        }
        __syncthreads();
    }

    float* o = outp + ((size_t)b * TT + t0) * HH;
    #pragma unroll
    for (int i = 0; i < 8; i++)
        #pragma unroll
        for (int j = 0; j < 8; j++)
            atomicAdd(&o[(size_t)(tyr * 8 + i) * HH + tx * 8 + j], acc[i][j]);
}

// ---------------------------------------------------------------------------
extern "C" void kernel_launch(void* const* d_in, const int* in_sizes, int n_in,
                              void* d_out, int out_size) {
    const float* x  = (const float*)d_in[0];
    const float* Wq = (const float*)d_in[1];
    const float* Wk = (const float*)d_in[2];
    const float* Wv = (const float*)d_in[3];
    float* out = (float*)d_out;

    cudaMemsetAsync(out, 0, (size_t)out_size * sizeof(float));
    qkv_kernel<<<dim3((BB * TT) / 128, 3), 128>>>(x, Wq, Wk, Wv);
    aff_kernel<<<dim3(TT / 128, TT / 128, BB), 256>>>();
    colsum_kernel<<<dim3(TT / 32, BB), 256>>>();
    out_kernel<<<dim3(TT / 128, 2, BB), 128>>>(out);
}

// round 5
// speedup vs baseline: 3.2871x; 1.9570x over previous
#include <cuda_runtime.h>
#include <cuda_bf16.h>
#include <cstdint>

#define BB 8
#define TT 2048
#define CC 1024
#define HH 64
#define SCALE 0.125f

// ---------------------------------------------------------------------------
// Device-global scratch
// ---------------------------------------------------------------------------
__device__ __nv_bfloat16 g_qh[(size_t)BB * TT * HH];
__device__ __nv_bfloat16 g_ql[(size_t)BB * TT * HH];
__device__ __nv_bfloat16 g_kh[(size_t)BB * TT * HH];
__device__ __nv_bfloat16 g_kl[(size_t)BB * TT * HH];
__device__ float         g_v [(size_t)BB * TT * HH];
__device__ __nv_bfloat16 g_Eh[(size_t)BB * TT * TT];   // 64 MB, [b][t][s]
__device__ __nv_bfloat16 g_El[(size_t)BB * TT * TT];   // 64 MB
__device__ float         g_Zpart[(size_t)BB * 16 * TT];
__device__ __nv_bfloat16 g_vTh[(size_t)BB * HH * TT];  // v' transposed [b][h][s]
__device__ __nv_bfloat16 g_vTl[(size_t)BB * HH * TT];

// ---------------------------------------------------------------------------
// Helpers
// ---------------------------------------------------------------------------
__device__ __forceinline__ uint32_t smem_u32(const void* p) {
    uint32_t a;
    asm("{ .reg .u64 t; cvta.to.shared.u64 t, %1; cvt.u32.u64 %0, t; }"
        : "=r"(a) : "l"(p));
    return a;
}

__device__ __forceinline__ void ldsm4(uint32_t r[4], uint32_t addr) {
    asm volatile("ldmatrix.sync.aligned.m8n8.x4.shared.b16 {%0,%1,%2,%3}, [%4];"
                 : "=r"(r[0]), "=r"(r[1]), "=r"(r[2]), "=r"(r[3]) : "r"(addr));
}

__device__ __forceinline__ void mma_bb(float c[4], const uint32_t a[4],
                                       uint32_t b0, uint32_t b1) {
    asm volatile(
        "mma.sync.aligned.m16n8k16.row.col.f32.bf16.bf16.f32 "
        "{%0,%1,%2,%3}, {%4,%5,%6,%7}, {%8,%9}, {%0,%1,%2,%3};"
        : "+f"(c[0]), "+f"(c[1]), "+f"(c[2]), "+f"(c[3])
        : "r"(a[0]), "r"(a[1]), "r"(a[2]), "r"(a[3]), "r"(b0), "r"(b1));
}

// split fp32 pair -> packed bf16x2 hi + lo (elem0 in low half)
__device__ __forceinline__ void split2(float f0, float f1, uint32_t& h, uint32_t& l) {
    __nv_bfloat16 h0 = __float2bfloat16_rn(f0);
    __nv_bfloat16 h1 = __float2bfloat16_rn(f1);
    float r0 = f0 - __bfloat162float(h0);
    float r1 = f1 - __bfloat162float(h1);
    __nv_bfloat16 l0 = __float2bfloat16_rn(r0);
    __nv_bfloat16 l1 = __float2bfloat16_rn(r1);
    uint16_t uh0 = *(uint16_t*)&h0, uh1 = *(uint16_t*)&h1;
    uint16_t ul0 = *(uint16_t*)&l0, ul1 = *(uint16_t*)&l1;
    h = (uint32_t)uh0 | ((uint32_t)uh1 << 16);
    l = (uint32_t)ul0 | ((uint32_t)ul1 << 16);
}

// ---------------------------------------------------------------------------
// Kernel 1: qkv. Grid (128, 3), 256 thr = 8 warps (4 m x 2 n).
// CTA tile: 128 rows x 64 cols, K=1024 in chunks of 32. 3-term split MMA.
// y==0 -> q (bf16 hi/lo), y==1 -> k (bf16 hi/lo), y==2 -> v (fp32).
// ---------------------------------------------------------------------------
__global__ __launch_bounds__(256) void qkv_kernel(const float* __restrict__ x,
                                                  const float* __restrict__ Wq,
                                                  const float* __restrict__ Wk,
                                                  const float* __restrict__ Wv) {
    __shared__ __align__(16) uint16_t sXH[128 * 40], sXL[128 * 40];
    __shared__ __align__(16) uint16_t sWH[64 * 40],  sWL[64 * 40];

    const int tid = threadIdx.x, wid = tid >> 5, lane = tid & 31;
    const int wm = wid >> 1, wn = wid & 1;
    const int y = blockIdx.y;
    const float* W = (y == 0) ? Wq : (y == 1) ? Wk : Wv;
    const int m0 = blockIdx.x * 128;

    const uint32_t xh_b = smem_u32(sXH), xl_b = smem_u32(sXL);
    const uint32_t wh_b = smem_u32(sWH), wl_b = smem_u32(sWL);

    float acc[2][4][4] = {};

    for (int c0 = 0; c0 < CC; c0 += 32) {
        #pragma unroll
        for (int it = 0; it < 4; it++) {
            int i = tid + it * 256;           // 1024 float4 loads
            int r = i >> 3, f4 = i & 7;
            float4 xv = *(const float4*)&x[(size_t)(m0 + r) * CC + c0 + f4 * 4];
            uint32_t h0, l0, h1, l1;
            split2(xv.x, xv.y, h0, l0);
            split2(xv.z, xv.w, h1, l1);
            int o = r * 40 + f4 * 4;
            *(uint32_t*)&sXH[o] = h0; *(uint32_t*)&sXH[o + 2] = h1;
            *(uint32_t*)&sXL[o] = l0; *(uint32_t*)&sXL[o + 2] = l1;
        }
        #pragma unroll
        for (int it = 0; it < 2; it++) {
            int i = tid + it * 256;           // 512 float4 loads
            int r = i >> 3, f4 = i & 7;
            float4 wv = *(const float4*)&W[(size_t)r * CC + c0 + f4 * 4];
            uint32_t h0, l0, h1, l1;
            split2(wv.x, wv.y, h0, l0);
            split2(wv.z, wv.w, h1, l1);
            int o = r * 40 + f4 * 4;
            *(uint32_t*)&sWH[o] = h0; *(uint32_t*)&sWH[o + 2] = h1;
            *(uint32_t*)&sWL[o] = l0; *(uint32_t*)&sWL[o + 2] = l1;
        }
        __syncthreads();

        #pragma unroll
        for (int j = 0; j < 2; j++) {         // two k16 steps
            uint32_t ah[2][4], al[2][4];
            #pragma unroll
            for (int mt = 0; mt < 2; mt++) {
                uint32_t ro = (uint32_t)(wm * 32 + mt * 16 + (lane & 15)) * 80
                            + j * 32 + (lane >> 4) * 16;
                ldsm4(ah[mt], xh_b + ro);
                ldsm4(al[mt], xl_b + ro);
            }
            uint32_t bh[2][4], bl[2][4];
            #pragma unroll
            for (int n16 = 0; n16 < 2; n16++) {
                uint32_t ro = (uint32_t)(wn * 32 + n16 * 16 + (lane & 7)
                            + ((lane >> 4) & 1) * 8) * 80
                            + ((lane >> 3) & 1) * 16 + j * 32;
                ldsm4(bh[n16], wh_b + ro);
                ldsm4(bl[n16], wl_b + ro);
            }
            #pragma unroll
            for (int mt = 0; mt < 2; mt++)
                #pragma unroll
                for (int nt = 0; nt < 4; nt++) {
                    int n16 = nt >> 1, o = (nt & 1) * 2;
                    mma_bb(acc[mt][nt], ah[mt], bh[n16][o], bh[n16][o + 1]);
                    mma_bb(acc[mt][nt], ah[mt], bl[n16][o], bl[n16][o + 1]);
                    mma_bb(acc[mt][nt], al[mt], bh[n16][o], bh[n16][o + 1]);
                }
        }
        __syncthreads();
    }

    // epilogue
    #pragma unroll
    for (int mt = 0; mt < 2; mt++)
        #pragma unroll
        for (int nt = 0; nt < 4; nt++) {
            int row0 = m0 + wm * 32 + mt * 16 + (lane >> 2);
            int cc = wn * 32 + nt * 8 + (lane & 3) * 2;
            if (y == 2) {
                *(float2*)&g_v[(size_t)row0 * HH + cc] =
                    make_float2(acc[mt][nt][0], acc[mt][nt][1]);
                *(float2*)&g_v[(size_t)(row0 + 8) * HH + cc] =
                    make_float2(acc[mt][nt][2], acc[mt][nt][3]);
            } else {
                uint32_t* gh = (uint32_t*)((y == 0) ? g_qh : g_kh);
                uint32_t* gl = (uint32_t*)((y == 0) ? g_ql : g_kl);
                uint32_t h, l;
                split2(acc[mt][nt][0], acc[mt][nt][1], h, l);
                gh[(size_t)row0 * 32 + (cc >> 1)] = h;
                gl[(size_t)row0 * 32 + (cc >> 1)] = l;
                split2(acc[mt][nt][2], acc[mt][nt][3], h, l);
                gh[(size_t)(row0 + 8) * 32 + (cc >> 1)] = h;
                gl[(size_t)(row0 + 8) * 32 + (cc >> 1)] = l;
            }
        }
}

// ---------------------------------------------------------------------------
// Kernel 2: E = exp(q k^T / 8) masked, + per-tile column partials.
// Grid (16 tt, 16 st, 8 b), lower-tri only. 256 thr = 8 warps (4 m x 2 n64).
// ---------------------------------------------------------------------------
__global__ __launch_bounds__(256) void aff_kernel() {
    const int tt = blockIdx.x, st = blockIdx.y, b = blockIdx.z;
    if (st > tt) return;
    extern __shared__ __align__(16) char ds[];
    const int tid = threadIdx.x, wid = tid >> 5, lane = tid & 31;
    const int wm = wid >> 1, wn = wid & 1;
    const int t0 = tt * 128, s0 = st * 128;

    // smem: QH 0, QL 18432, KH 36864, KL 55296 (each 128 rows x 72 bf16)
    const uint32_t qh_b = smem_u32(ds);
    const uint32_t ql_b = qh_b + 18432, kh_b = qh_b + 36864, kl_b = qh_b + 55296;
    float* es = (float*)ds;                   // overlay, stride 132 floats

    const uint32_t* qhg = (const uint32_t*)g_qh + ((size_t)b * TT + t0) * 32;
    const uint32_t* qlg = (const uint32_t*)g_ql + ((size_t)b * TT + t0) * 32;
    const uint32_t* khg = (const uint32_t*)g_kh + ((size_t)b * TT + s0) * 32;
    const uint32_t* klg = (const uint32_t*)g_kl + ((size_t)b * TT + s0) * 32;
    #pragma unroll
    for (int it = 0; it < 16; it++) {
        int i = tid + it * 256;               // 4096 per buffer
        int r = i >> 5, c = i & 31;
        uint32_t o = (uint32_t)r * 144 + c * 4;
        *(uint32_t*)(ds + o)         = qhg[(size_t)r * 32 + c];
        *(uint32_t*)(ds + 18432 + o) = qlg[(size_t)r * 32 + c];
        *(uint32_t*)(ds + 36864 + o) = khg[(size_t)r * 32 + c];
        *(uint32_t*)(ds + 55296 + o) = klg[(size_t)r * 32 + c];
    }
    __syncthreads();

    float acc[2][8][4] = {};
    #pragma unroll
    for (int j = 0; j < 4; j++) {             // k16 over K=64
        uint32_t ah[2][4], al[2][4];
        #pragma unroll
        for (int mt = 0; mt < 2; mt++) {
            uint32_t ro = (uint32_t)(wm * 32 + mt * 16 + (lane & 15)) * 144
                        + j * 32 + (lane >> 4) * 16;
            ldsm4(ah[mt], qh_b + ro);
            ldsm4(al[mt], ql_b + ro);
        }
        uint32_t bh[4][4], bl[4][4];
        #pragma unroll
        for (int n16 = 0; n16 < 4; n16++) {
            uint32_t ro = (uint32_t)(wn * 64 + n16 * 16 + (lane & 7)
                        + ((lane >> 4) & 1) * 8) * 144
                        + ((lane >> 3) & 1) * 16 + j * 32;
            ldsm4(bh[n16], kh_b + ro);
            ldsm4(bl[n16], kl_b + ro);
        }
        #pragma unroll
        for (int mt = 0; mt < 2; mt++)
            #pragma unroll
            for (int nt = 0; nt < 8; nt++) {
                int n16 = nt >> 1, o = (nt & 1) * 2;
                mma_bb(acc[mt][nt], ah[mt], bh[n16][o], bh[n16][o + 1]);
                mma_bb(acc[mt][nt], ah[mt], bl[n16][o], bl[n16][o + 1]);
                mma_bb(acc[mt][nt], al[mt], bh[n16][o], bh[n16][o + 1]);
            }
    }
    __syncthreads();                          // before es overlay writes

    uint32_t* EhU = (uint32_t*)g_Eh;
    uint32_t* ElU = (uint32_t*)g_El;
    #pragma unroll
    for (int mt = 0; mt < 2; mt++)
        #pragma unroll
        for (int nt = 0; nt < 8; nt++) {
            int tl0 = wm * 32 + mt * 16 + (lane >> 2);
            int sl  = wn * 64 + nt * 8 + (lane & 3) * 2;
            int tg0 = t0 + tl0, sc = s0 + sl;
            float e0 = (sc     <= tg0) ? __expf(acc[mt][nt][0] * SCALE) : 0.f;
            float e1 = (sc + 1 <= tg0) ? __expf(acc[mt][nt][1] * SCALE) : 0.f;
            float e2 = (sc     <= tg0 + 8) ? __expf(acc[mt][nt][2] * SCALE) : 0.f;
            float e3 = (sc + 1 <= tg0 + 8) ? __expf(acc[mt][nt][3] * SCALE) : 0.f;
            uint32_t h, l;
            split2(e0, e1, h, l);
            EhU[((size_t)b * TT + tg0) * 1024 + (sc >> 1)] = h;
            ElU[((size_t)b * TT + tg0) * 1024 + (sc >> 1)] = l;
            split2(e2, e3, h, l);
            EhU[((size_t)b * TT + tg0 + 8) * 1024 + (sc >> 1)] = h;
            ElU[((size_t)b * TT + tg0 + 8) * 1024 + (sc >> 1)] = l;
            es[tl0 * 132 + sl] = e0;       es[tl0 * 132 + sl + 1] = e1;
            es[(tl0 + 8) * 132 + sl] = e2; es[(tl0 + 8) * 132 + sl + 1] = e3;
        }
    __syncthreads();

    if (tid < 128) {
        float z = 0.f;
        #pragma unroll 8
        for (int t = 0; t < 128; t++) z += es[t * 132 + tid];
        g_Zpart[((size_t)b * 16 + tt) * TT + s0 + tid] = z;
    }
}

// ---------------------------------------------------------------------------
// Kernel 3: Z_s, then v'[s] = v[s]/Z_s written transposed hi/lo [b][h][s].
// ---------------------------------------------------------------------------
__global__ __launch_bounds__(128) void colsum_kernel() {
    const int b = blockIdx.y;
    const int s = blockIdx.x * 128 + threadIdx.x;
    float z = 0.f;
    for (int tt = s >> 7; tt < 16; tt++)
        z += g_Zpart[((size_t)b * 16 + tt) * TT + s];
    const float inv = 1.0f / z;
    const float* vp = g_v + ((size_t)b * TT + s) * HH;
    #pragma unroll
    for (int h = 0; h < HH; h++) {
        float vv = vp[h] * inv;
        __nv_bfloat16 hi = __float2bfloat16_rn(vv);
        float r = vv - __bfloat162float(hi);
        __nv_bfloat16 lo = __float2bfloat16_rn(r);
        g_vTh[((size_t)b * HH + h) * TT + s] = hi;
        g_vTl[((size_t)b * HH + h) * TT + s] = lo;
    }
}

// ---------------------------------------------------------------------------
// Kernel 4: out = E @ v'. Grid (16 tt, 2 split, 8 b). 256 thr (4 m x 2 n).
// K = s in chunks of 64 up to diagonal, interleaved split-K, atomicAdd (2
// commutative terms -> deterministic). Operands already bf16 hi/lo.
// ---------------------------------------------------------------------------
__global__ __launch_bounds__(256) void out_kernel(float* __restrict__ outp) {
    const int tt = blockIdx.x, split = blockIdx.y, b = blockIdx.z;
    const int t0 = tt * 128;
    const int nchunk = 2 * (tt + 1);
    extern __shared__ __align__(16) char ds[];
    const int tid = threadIdx.x, wid = tid >> 5, lane = tid & 31;
    const int wm = wid >> 1, wn = wid & 1;

    // smem: EH 0 (128x72), EL 18432, VH 36864 (64x72), VL 46080; total 55296
    const uint32_t eh_b = smem_u32(ds);
    const uint32_t el_b = eh_b + 18432, vh_b = eh_b + 36864, vl_b = eh_b + 46080;

    const uint32_t* EhU = (const uint32_t*)g_Eh + ((size_t)b * TT + t0) * 1024;
    const uint32_t* ElU = (const uint32_t*)g_El + ((size_t)b * TT + t0) * 1024;
    const uint32_t* VhU = (const uint32_t*)g_vTh + (size_t)b * HH * 1024;
    const uint32_t* VlU = (const uint32_t*)g_vTl + (size_t)b * HH * 1024;

    float acc[2][4][4] = {};

    for (int c = split; c < nchunk; c += 2) {
        const int s32 = c * 32;               // uint32 col offset (64 bf16)
        #pragma unroll
        for (int it = 0; it < 16; it++) {
            int i = tid + it * 256;
            int r = i >> 5, cc = i & 31;
            uint32_t o = (uint32_t)r * 144 + cc * 4;
            *(uint32_t*)(ds + o)         = EhU[(size_t)r * 1024 + s32 + cc];
            *(uint32_t*)(ds + 18432 + o) = ElU[(size_t)r * 1024 + s32 + cc];
        }
        #pragma unroll
        for (int it = 0; it < 8; it++) {
            int i = tid + it * 256;
            int r = i >> 5, cc = i & 31;
            uint32_t o = (uint32_t)r * 144 + cc * 4;
            *(uint32_t*)(ds + 36864 + o) = VhU[(size_t)r * 1024 + s32 + cc];
            *(uint32_t*)(ds + 46080 + o) = VlU[(size_t)r * 1024 + s32 + cc];
        }
        __syncthreads();

        #pragma unroll
        for (int j = 0; j < 4; j++) {
            uint32_t ah[2][4], al[2][4];
            #pragma unroll
            for (int mt = 0; mt < 2; mt++) {
                uint32_t ro = (uint32_t)(wm * 32 + mt * 16 + (lane & 15)) * 144
                            + j * 32 + (lane >> 4) * 16;
                ldsm4(ah[mt], eh_b + ro);
                ldsm4(al[mt], el_b + ro);
            }
            uint32_t bh[2][4], bl[2][4];
            #pragma unroll
            for (int n16 = 0; n16 < 2; n16++) {
                uint32_t ro = (uint32_t)(wn * 32 + n16 * 16 + (lane & 7)
                            + ((lane >> 4) & 1) * 8) * 144
                            + ((lane >> 3) & 1) * 16 + j * 32;
                ldsm4(bh[n16], vh_b + ro);
                ldsm4(bl[n16], vl_b + ro);
            }
            #pragma unroll
            for (int mt = 0; mt < 2; mt++)
                #pragma unroll
                for (int nt = 0; nt < 4; nt++) {
                    int n16 = nt >> 1, o = (nt & 1) * 2;
                    mma_bb(acc[mt][nt], ah[mt], bh[n16][o], bh[n16][o + 1]);
                    mma_bb(acc[mt][nt], ah[mt], bl[n16][o], bl[n16][o + 1]);
                    mma_bb(acc[mt][nt], al[mt], bh[n16][o], bh[n16][o + 1]);
                }
        }
        __syncthreads();
    }

    #pragma unroll
    for (int mt = 0; mt < 2; mt++)
        #pragma unroll
        for (int nt = 0; nt < 4; nt++) {
            int row0 = t0 + wm * 32 + mt * 16 + (lane >> 2);
            int cc = wn * 32 + nt * 8 + (lane & 3) * 2;
            float* o0 = &outp[((size_t)b * TT + row0) * HH + cc];
            float* o1 = &outp[((size_t)b * TT + row0 + 8) * HH + cc];
            atomicAdd(o0,     acc[mt][nt][0]);
            atomicAdd(o0 + 1, acc[mt][nt][1]);
            atomicAdd(o1,     acc[mt][nt][2]);
            atomicAdd(o1 + 1, acc[mt][nt][3]);
        }
}

// ---------------------------------------------------------------------------
extern "C" void kernel_launch(void* const* d_in, const int* in_sizes, int n_in,
                              void* d_out, int out_size) {
    const float* x  = (const float*)d_in[0];
    const float* Wq = (const float*)d_in[1];
    const float* Wk = (const float*)d_in[2];
    const float* Wv = (const float*)d_in[3];
    float* out = (float*)d_out;

    cudaFuncSetAttribute(aff_kernel, cudaFuncAttributeMaxDynamicSharedMemorySize, 73728);
    cudaFuncSetAttribute(out_kernel, cudaFuncAttributeMaxDynamicSharedMemorySize, 55296);

    cudaMemsetAsync(out, 0, (size_t)out_size * sizeof(float));
    qkv_kernel<<<dim3((BB * TT) / 128, 3), 256>>>(x, Wq, Wk, Wv);
    aff_kernel<<<dim3(16, 16, BB), 256, 73728>>>();
    colsum_kernel<<<dim3(16, BB), 128>>>();
    out_kernel<<<dim3(16, 2, BB), 256, 55296>>>(out);
}

// round 8
// speedup vs baseline: 3.3734x; 1.0263x over previous
#include <cuda_runtime.h>
#include <cuda_bf16.h>
#include <cuda_fp16.h>
#include <cstdint>

#define BB 8
#define TT 2048
#define CC 1024
#define HH 64
#define SCALE 0.125f

// ---------------------------------------------------------------------------
// Device-global scratch
// ---------------------------------------------------------------------------
__device__ __nv_bfloat16 g_qh[(size_t)BB * TT * HH];
__device__ __nv_bfloat16 g_ql[(size_t)BB * TT * HH];
__device__ __nv_bfloat16 g_kh[(size_t)BB * TT * HH];
__device__ __nv_bfloat16 g_kl[(size_t)BB * TT * HH];
__device__ float         g_v [(size_t)BB * TT * HH];
__device__ __half        g_Ef[(size_t)BB * TT * TT];   // 64 MB, fp16 [b][t][s]
__device__ float         g_Zpart[(size_t)BB * 16 * TT];
__device__ __half        g_vTh[(size_t)BB * HH * TT];  // v' hi, [b][h][s]
__device__ __half        g_vTl[(size_t)BB * HH * TT];  // v' lo

// ---------------------------------------------------------------------------
// Helpers
// ---------------------------------------------------------------------------
__device__ __forceinline__ uint32_t smem_u32(const void* p) {
    uint32_t a;
    asm("{ .reg .u64 t; cvta.to.shared.u64 t, %1; cvt.u32.u64 %0, t; }"
        : "=r"(a) : "l"(p));
    return a;
}

__device__ __forceinline__ void ldsm4(uint32_t r[4], uint32_t addr) {
    asm volatile("ldmatrix.sync.aligned.m8n8.x4.shared.b16 {%0,%1,%2,%3}, [%4];"
                 : "=r"(r[0]), "=r"(r[1]), "=r"(r[2]), "=r"(r[3]) : "r"(addr));
}

__device__ __forceinline__ void mma_bb(float c[4], const uint32_t a[4],
                                       uint32_t b0, uint32_t b1) {
    asm volatile(
        "mma.sync.aligned.m16n8k16.row.col.f32.bf16.bf16.f32 "
        "{%0,%1,%2,%3}, {%4,%5,%6,%7}, {%8,%9}, {%0,%1,%2,%3};"
        : "+f"(c[0]), "+f"(c[1]), "+f"(c[2]), "+f"(c[3])
        : "r"(a[0]), "r"(a[1]), "r"(a[2]), "r"(a[3]), "r"(b0), "r"(b1));
}

__device__ __forceinline__ void mma_ff(float c[4], const uint32_t a[4],
                                       uint32_t b0, uint32_t b1) {
    asm volatile(
        "mma.sync.aligned.m16n8k16.row.col.f32.f16.f16.f32 "
        "{%0,%1,%2,%3}, {%4,%5,%6,%7}, {%8,%9}, {%0,%1,%2,%3};"
        : "+f"(c[0]), "+f"(c[1]), "+f"(c[2]), "+f"(c[3])
        : "r"(a[0]), "r"(a[1]), "r"(a[2]), "r"(a[3]), "r"(b0), "r"(b1));
}

// split fp32 pair -> packed bf16x2 hi + lo (elem0 in low half)
__device__ __forceinline__ void split2(float f0, float f1, uint32_t& h, uint32_t& l) {
    __nv_bfloat16 h0 = __float2bfloat16_rn(f0);
    __nv_bfloat16 h1 = __float2bfloat16_rn(f1);
    float r0 = f0 - __bfloat162float(h0);
    float r1 = f1 - __bfloat162float(h1);
    __nv_bfloat16 l0 = __float2bfloat16_rn(r0);
    __nv_bfloat16 l1 = __float2bfloat16_rn(r1);
    uint16_t uh0 = *(uint16_t*)&h0, uh1 = *(uint16_t*)&h1;
    uint16_t ul0 = *(uint16_t*)&l0, ul1 = *(uint16_t*)&l1;
    h = (uint32_t)uh0 | ((uint32_t)uh1 << 16);
    l = (uint32_t)ul0 | ((uint32_t)ul1 << 16);
}

__device__ __forceinline__ uint32_t packh2(float f0, float f1) {
    __half2 hh = __floats2half2_rn(f0, f1);
    return *(uint32_t*)&hh;
}

// ---------------------------------------------------------------------------
// Kernel 1: merged qkv. Grid 128, 512 thr = 16 warps (4 m x 4 n).
// CTA tile 128 rows x 192 cols (q|k|v), K=1024 in chunks of 32, 3-term split.
// x loaded & split ONCE per CTA. q,k -> bf16 hi/lo; v -> fp32.
// smem: XH 10240 | XL 10240 | WH 15360 | WL 15360 = 51200 B (dynamic)
// ---------------------------------------------------------------------------
__global__ __launch_bounds__(512) void qkv_kernel(const float* __restrict__ x,
                                                  const float* __restrict__ Wq,
                                                  const float* __restrict__ Wk,
                                                  const float* __restrict__ Wv) {
    extern __shared__ __align__(16) char ds[];
    const uint32_t xh_b = smem_u32(ds);
    const uint32_t xl_b = xh_b + 10240, wh_b = xh_b + 20480, wl_b = xh_b + 35840;

    const int tid = threadIdx.x, wid = tid >> 5, lane = tid & 31;
    const int wm = wid >> 2, wn = wid & 3;
    const int m0 = blockIdx.x * 128;

    float acc[2][6][4] = {};

    for (int c0 = 0; c0 < CC; c0 += 32) {
        #pragma unroll
        for (int it = 0; it < 2; it++) {
            int i = tid + it * 512;           // 1024 float4
            int r = i >> 3, f4 = i & 7;
            float4 xv = *(const float4*)&x[(size_t)(m0 + r) * CC + c0 + f4 * 4];
            uint32_t h0, l0, h1, l1;
            split2(xv.x, xv.y, h0, l0);
            split2(xv.z, xv.w, h1, l1);
            uint32_t o = (uint32_t)r * 80 + f4 * 8;
            *(uint32_t*)(ds + o)          = h0; *(uint32_t*)(ds + o + 4)          = h1;
            *(uint32_t*)(ds + 10240 + o)  = l0; *(uint32_t*)(ds + 10240 + o + 4)  = l1;
        }
        #pragma unroll
        for (int it = 0; it < 3; it++) {
            int i = tid + it * 512;           // 1536 float4
            int r = i >> 3, f4 = i & 7;
            const float* Wp = (r < 64) ? Wq : (r < 128) ? Wk : Wv;
            int row = r & 63;
            float4 wv = *(const float4*)&Wp[(size_t)row * CC + c0 + f4 * 4];
            uint32_t h0, l0, h1, l1;
            split2(wv.x, wv.y, h0, l0);
            split2(wv.z, wv.w, h1, l1);
            uint32_t o = (uint32_t)r * 80 + f4 * 8;
            *(uint32_t*)(ds + 20480 + o) = h0; *(uint32_t*)(ds + 20480 + o + 4) = h1;
            *(uint32_t*)(ds + 35840 + o) = l0; *(uint32_t*)(ds + 35840 + o + 4) = l1;
        }
        __syncthreads();

        #pragma unroll
        for (int j = 0; j < 2; j++) {
            uint32_t ah[2][4], al[2][4];
            #pragma unroll
            for (int mt = 0; mt < 2; mt++) {
                uint32_t ro = (uint32_t)(wm * 32 + mt * 16 + (lane & 15)) * 80
                            + j * 32 + (lane >> 4) * 16;
                ldsm4(ah[mt], xh_b + ro);
                ldsm4(al[mt], xl_b + ro);
            }
            uint32_t bh[3][4], bl[3][4];
            #pragma unroll
            for (int n16 = 0; n16 < 3; n16++) {
                uint32_t ro = (uint32_t)(wn * 48 + n16 * 16 + (lane & 7)
                            + ((lane >> 4) & 1) * 8) * 80
                            + ((lane >> 3) & 1) * 16 + j * 32;
                ldsm4(bh[n16], wh_b + ro);
                ldsm4(bl[n16], wl_b + ro);
            }
            #pragma unroll
            for (int mt = 0; mt < 2; mt++)
                #pragma unroll
                for (int nt = 0; nt < 6; nt++) {
                    int n16 = nt >> 1, o = (nt & 1) * 2;
                    mma_bb(acc[mt][nt], ah[mt], bh[n16][o], bh[n16][o + 1]);
                    mma_bb(acc[mt][nt], ah[mt], bl[n16][o], bl[n16][o + 1]);
                    mma_bb(acc[mt][nt], al[mt], bh[n16][o], bh[n16][o + 1]);
                }
        }
        __syncthreads();
    }

    #pragma unroll
    for (int mt = 0; mt < 2; mt++)
        #pragma unroll
        for (int nt = 0; nt < 6; nt++) {
            int row0 = m0 + wm * 32 + mt * 16 + (lane >> 2);
            int cc = wn * 48 + nt * 8 + (lane & 3) * 2;
            if (cc < 128) {
                uint32_t* gh = (uint32_t*)((cc < 64) ? g_qh : g_kh);
                uint32_t* gl = (uint32_t*)((cc < 64) ? g_ql : g_kl);
                int col = cc & 63;
                uint32_t h, l;
                split2(acc[mt][nt][0], acc[mt][nt][1], h, l);
                gh[(size_t)row0 * 32 + (col >> 1)] = h;
                gl[(size_t)row0 * 32 + (col >> 1)] = l;
                split2(acc[mt][nt][2], acc[mt][nt][3], h, l);
                gh[(size_t)(row0 + 8) * 32 + (col >> 1)] = h;
                gl[(size_t)(row0 + 8) * 32 + (col >> 1)] = l;
            } else {
                int col = cc - 128;
                *(float2*)&g_v[(size_t)row0 * HH + col] =
                    make_float2(acc[mt][nt][0], acc[mt][nt][1]);
                *(float2*)&g_v[(size_t)(row0 + 8) * HH + col] =
                    make_float2(acc[mt][nt][2], acc[mt][nt][3]);
            }
        }
}

// ---------------------------------------------------------------------------
// Kernel 2: E = exp(q k^T / 8) masked (fp16), + per-tile column partials.
// Grid (16 tt, 16 st, 8 b), lower-tri only. 256 thr = 8 warps (4 m x 2 n64).
// ---------------------------------------------------------------------------
__global__ __launch_bounds__(256) void aff_kernel() {
    const int tt = blockIdx.x, st = blockIdx.y, b = blockIdx.z;
    if (st > tt) return;
    extern __shared__ __align__(16) char ds[];
    const int tid = threadIdx.x, wid = tid >> 5, lane = tid & 31;
    const int wm = wid >> 1, wn = wid & 1;
    const int t0 = tt * 128, s0 = st * 128;

    const uint32_t qh_b = smem_u32(ds);
    const uint32_t ql_b = qh_b + 18432, kh_b = qh_b + 36864, kl_b = qh_b + 55296;
    float* es = (float*)ds;                   // overlay, stride 132 floats

    const uint32_t* qhg = (const uint32_t*)g_qh + ((size_t)b * TT + t0) * 32;
    const uint32_t* qlg = (const uint32_t*)g_ql + ((size_t)b * TT + t0) * 32;
    const uint32_t* khg = (const uint32_t*)g_kh + ((size_t)b * TT + s0) * 32;
    const uint32_t* klg = (const uint32_t*)g_kl + ((size_t)b * TT + s0) * 32;
    #pragma unroll
    for (int it = 0; it < 16; it++) {
        int i = tid + it * 256;
        int r = i >> 5, c = i & 31;
        uint32_t o = (uint32_t)r * 144 + c * 4;
        *(uint32_t*)(ds + o)         = qhg[(size_t)r * 32 + c];
        *(uint32_t*)(ds + 18432 + o) = qlg[(size_t)r * 32 + c];
        *(uint32_t*)(ds + 36864 + o) = khg[(size_t)r * 32 + c];
        *(uint32_t*)(ds + 55296 + o) = klg[(size_t)r * 32 + c];
    }
    __syncthreads();

    float acc[2][8][4] = {};
    #pragma unroll
    for (int j = 0; j < 4; j++) {
        uint32_t ah[2][4], al[2][4];
        #pragma unroll
        for (int mt = 0; mt < 2; mt++) {
            uint32_t ro = (uint32_t)(wm * 32 + mt * 16 + (lane & 15)) * 144
                        + j * 32 + (lane >> 4) * 16;
            ldsm4(ah[mt], qh_b + ro);
            ldsm4(al[mt], ql_b + ro);
        }
        uint32_t bh[4][4], bl[4][4];
        #pragma unroll
        for (int n16 = 0; n16 < 4; n16++) {
            uint32_t ro = (uint32_t)(wn * 64 + n16 * 16 + (lane & 7)
                        + ((lane >> 4) & 1) * 8) * 144
                        + ((lane >> 3) & 1) * 16 + j * 32;
            ldsm4(bh[n16], kh_b + ro);
            ldsm4(bl[n16], kl_b + ro);
        }
        #pragma unroll
        for (int mt = 0; mt < 2; mt++)
            #pragma unroll
            for (int nt = 0; nt < 8; nt++) {
                int n16 = nt >> 1, o = (nt & 1) * 2;
                mma_bb(acc[mt][nt], ah[mt], bh[n16][o], bh[n16][o + 1]);
                mma_bb(acc[mt][nt], ah[mt], bl[n16][o], bl[n16][o + 1]);
                mma_bb(acc[mt][nt], al[mt], bh[n16][o], bh[n16][o + 1]);
            }
    }
    __syncthreads();                          // before es overlay writes

    uint32_t* EfU = (uint32_t*)g_Ef;
    #pragma unroll
    for (int mt = 0; mt < 2; mt++)
        #pragma unroll
        for (int nt = 0; nt < 8; nt++) {
            int tl0 = wm * 32 + mt * 16 + (lane >> 2);
            int sl  = wn * 64 + nt * 8 + (lane & 3) * 2;
            int tg0 = t0 + tl0, sc = s0 + sl;
            float e0 = (sc     <= tg0) ? __expf(acc[mt][nt][0] * SCALE) : 0.f;
            float e1 = (sc + 1 <= tg0) ? __expf(acc[mt][nt][1] * SCALE) : 0.f;
            float e2 = (sc     <= tg0 + 8) ? __expf(acc[mt][nt][2] * SCALE) : 0.f;
            float e3 = (sc + 1 <= tg0 + 8) ? __expf(acc[mt][nt][3] * SCALE) : 0.f;
            EfU[((size_t)b * TT + tg0)     * 1024 + (sc >> 1)] = packh2(e0, e1);
            EfU[((size_t)b * TT + tg0 + 8) * 1024 + (sc >> 1)] = packh2(e2, e3);
            es[tl0 * 132 + sl] = e0;       es[tl0 * 132 + sl + 1] = e1;
            es[(tl0 + 8) * 132 + sl] = e2; es[(tl0 + 8) * 132 + sl + 1] = e3;
        }
    __syncthreads();

    if (tid < 128) {
        float z = 0.f;
        #pragma unroll 8
        for (int t = 0; t < 128; t++) z += es[t * 132 + tid];
        g_Zpart[((size_t)b * 16 + tt) * TT + s0 + tid] = z;
    }
}

// ---------------------------------------------------------------------------
// Kernel 3: Z_s, then v'[s] = v[s]/Z_s written transposed fp16 hi/lo [b][h][s].
// ---------------------------------------------------------------------------
__global__ __launch_bounds__(128) void colsum_kernel() {
    const int b = blockIdx.y;
    const int s = blockIdx.x * 128 + threadIdx.x;
    float z = 0.f;
    for (int tt = s >> 7; tt < 16; tt++)
        z += g_Zpart[((size_t)b * 16 + tt) * TT + s];
    const float inv = 1.0f / z;
    const float* vp = g_v + ((size_t)b * TT + s) * HH;
    #pragma unroll
    for (int h = 0; h < HH; h++) {
        float vv = vp[h] * inv;
        __half hi = __float2half_rn(vv);
        __half lo = __float2half_rn(vv - __half2float(hi));
        g_vTh[((size_t)b * HH + h) * TT + s] = hi;
        g_vTl[((size_t)b * HH + h) * TT + s] = lo;
    }
}

// ---------------------------------------------------------------------------
// Kernel 4: out = E @ v' (fp16 x fp16-hi/lo, 2 terms). Grid (16 tt, 2, 8 b).
// 256 thr (4 m x 2 n). Interleaved split-K + atomicAdd (2 commutative adds).
// smem: E 18432 | VH 9216 | VL 9216 = 36864 B
// ---------------------------------------------------------------------------
__global__ __launch_bounds__(256) void out_kernel(float* __restrict__ outp) {
    const int tt = blockIdx.x, split = blockIdx.y, b = blockIdx.z;
    const int t0 = tt * 128;
    const int nchunk = 2 * (tt + 1);
    extern __shared__ __align__(16) char ds[];
    const int tid = threadIdx.x, wid = tid >> 5, lane = tid & 31;
    const int wm = wid >> 1, wn = wid & 1;

    const uint32_t ef_b = smem_u32(ds);
    const uint32_t vh_b = ef_b + 18432, vl_b = ef_b + 27648;

    const uint32_t* EfU = (const uint32_t*)g_Ef + ((size_t)b * TT + t0) * 1024;
    const uint32_t* VhU = (const uint32_t*)g_vTh + (size_t)b * HH * 1024;
    const uint32_t* VlU = (const uint32_t*)g_vTl + (size_t)b * HH * 1024;

    float acc[2][4][4] = {};

    for (int c = split; c < nchunk; c += 2) {
        const int s32 = c * 32;
        #pragma unroll
        for (int it = 0; it < 16; it++) {
            int i = tid + it * 256;
            int r = i >> 5, cc = i & 31;
            *(uint32_t*)(ds + (uint32_t)r * 144 + cc * 4) =
                EfU[(size_t)r * 1024 + s32 + cc];
        }
        #pragma unroll
        for (int it = 0; it < 8; it++) {
            int i = tid + it * 256;
            int r = i >> 5, cc = i & 31;
            uint32_t o = (uint32_t)r * 144 + cc * 4;
            *(uint32_t*)(ds + 18432 + o) = VhU[(size_t)r * 1024 + s32 + cc];
            *(uint32_t*)(ds + 27648 + o) = VlU[(size_t)r * 1024 + s32 + cc];
        }
        __syncthreads();

        #pragma unroll
        for (int j = 0; j < 4; j++) {
            uint32_t ae[2][4];
            #pragma unroll
            for (int mt = 0; mt < 2; mt++) {
                uint32_t ro = (uint32_t)(wm * 32 + mt * 16 + (lane & 15)) * 144
                            + j * 32 + (lane >> 4) * 16;
                ldsm4(ae[mt], ef_b + ro);
            }
            uint32_t bh[2][4], bl[2][4];
            #pragma unroll
            for (int n16 = 0; n16 < 2; n16++) {
                uint32_t ro = (uint32_t)(wn * 32 + n16 * 16 + (lane & 7)
                            + ((lane >> 4) & 1) * 8) * 144
                            + ((lane >> 3) & 1) * 16 + j * 32;
                ldsm4(bh[n16], vh_b + ro);
                ldsm4(bl[n16], vl_b + ro);
            }
            #pragma unroll
            for (int mt = 0; mt < 2; mt++)
                #pragma unroll
                for (int nt = 0; nt < 4; nt++) {
                    int n16 = nt >> 1, o = (nt & 1) * 2;
                    mma_ff(acc[mt][nt], ae[mt], bh[n16][o], bh[n16][o + 1]);
                    mma_ff(acc[mt][nt], ae[mt], bl[n16][o], bl[n16][o + 1]);
                }
        }
        __syncthreads();
    }

    #pragma unroll
    for (int mt = 0; mt < 2; mt++)
        #pragma unroll
        for (int nt = 0; nt < 4; nt++) {
            int row0 = t0 + wm * 32 + mt * 16 + (lane >> 2);
            int cc = wn * 32 + nt * 8 + (lane & 3) * 2;
            float* o0 = &outp[((size_t)b * TT + row0) * HH + cc];
            float* o1 = &outp[((size_t)b * TT + row0 + 8) * HH + cc];
            atomicAdd(o0,     acc[mt][nt][0]);
            atomicAdd(o0 + 1, acc[mt][nt][1]);
            atomicAdd(o1,     acc[mt][nt][2]);
            atomicAdd(o1 + 1, acc[mt][nt][3]);
        }
}

// ---------------------------------------------------------------------------
extern "C" void kernel_launch(void* const* d_in, const int* in_sizes, int n_in,
                              void* d_out, int out_size) {
    const float* x  = (const float*)d_in[0];
    const float* Wq = (const float*)d_in[1];
    const float* Wk = (const float*)d_in[2];
    const float* Wv = (const float*)d_in[3];
    float* out = (float*)d_out;

    cudaFuncSetAttribute(qkv_kernel, cudaFuncAttributeMaxDynamicSharedMemorySize, 51200);
    cudaFuncSetAttribute(aff_kernel, cudaFuncAttributeMaxDynamicSharedMemorySize, 73728);
    cudaFuncSetAttribute(out_kernel, cudaFuncAttributeMaxDynamicSharedMemorySize, 36864);

    cudaMemsetAsync(out, 0, (size_t)out_size * sizeof(float));
    qkv_kernel<<<(BB * TT) / 128, 512, 51200>>>(x, Wq, Wk, Wv);
    aff_kernel<<<dim3(16, 16, BB), 256, 73728>>>();
    colsum_kernel<<<dim3(16, BB), 128>>>();
    out_kernel<<<dim3(16, 2, BB), 256, 36864>>>(out);
}

// round 12
// speedup vs baseline: 3.5262x; 1.0453x over previous
#include <cuda_runtime.h>
#include <cuda_bf16.h>
#include <cuda_fp16.h>
#include <cstdint>

#define BB 8
#define TT 2048
#define CC 1024
#define HH 64
#define SCALE 0.125f

// ---------------------------------------------------------------------------
// Device-global scratch (16B-aligned for uint4 / cp.async access)
// ---------------------------------------------------------------------------
__device__ __align__(16) __nv_bfloat16 g_qh[(size_t)BB * TT * HH];
__device__ __align__(16) __nv_bfloat16 g_ql[(size_t)BB * TT * HH];
__device__ __align__(16) __nv_bfloat16 g_kh[(size_t)BB * TT * HH];
__device__ __align__(16) __nv_bfloat16 g_kl[(size_t)BB * TT * HH];
__device__ __align__(16) float         g_v [(size_t)BB * TT * HH];
__device__ __align__(16) float         g_Zpart[(size_t)BB * 16 * TT];
__device__ __align__(16) __half        g_vTh[(size_t)BB * HH * TT];  // [b][h][s]
__device__ __align__(16) __half        g_vTl[(size_t)BB * HH * TT];

// ---------------------------------------------------------------------------
// Helpers
// ---------------------------------------------------------------------------
__device__ __forceinline__ uint32_t smem_u32(const void* p) {
    uint32_t a;
    asm("{ .reg .u64 t; cvta.to.shared.u64 t, %1; cvt.u32.u64 %0, t; }"
        : "=r"(a) : "l"(p));
    return a;
}

__device__ __forceinline__ void ldsm4(uint32_t r[4], uint32_t addr) {
    asm volatile("ldmatrix.sync.aligned.m8n8.x4.shared.b16 {%0,%1,%2,%3}, [%4];"
                 : "=r"(r[0]), "=r"(r[1]), "=r"(r[2]), "=r"(r[3]) : "r"(addr));
}

__device__ __forceinline__ void mma_bb(float c[4], const uint32_t a[4],
                                       uint32_t b0, uint32_t b1) {
    asm volatile(
        "mma.sync.aligned.m16n8k16.row.col.f32.bf16.bf16.f32 "
        "{%0,%1,%2,%3}, {%4,%5,%6,%7}, {%8,%9}, {%0,%1,%2,%3};"
        : "+f"(c[0]), "+f"(c[1]), "+f"(c[2]), "+f"(c[3])
        : "r"(a[0]), "r"(a[1]), "r"(a[2]), "r"(a[3]), "r"(b0), "r"(b1));
}

__device__ __forceinline__ void mma_ff(float c[4], const uint32_t a[4],
                                       uint32_t b0, uint32_t b1) {
    asm volatile(
        "mma.sync.aligned.m16n8k16.row.col.f32.f16.f16.f32 "
        "{%0,%1,%2,%3}, {%4,%5,%6,%7}, {%8,%9}, {%0,%1,%2,%3};"
        : "+f"(c[0]), "+f"(c[1]), "+f"(c[2]), "+f"(c[3])
        : "r"(a[0]), "r"(a[1]), "r"(a[2]), "r"(a[3]), "r"(b0), "r"(b1));
}

__device__ __forceinline__ void split2(float f0, float f1, uint32_t& h, uint32_t& l) {
    __nv_bfloat16 h0 = __float2bfloat16_rn(f0);
    __nv_bfloat16 h1 = __float2bfloat16_rn(f1);
    float r0 = f0 - __bfloat162float(h0);
    float r1 = f1 - __bfloat162float(h1);
    __nv_bfloat16 l0 = __float2bfloat16_rn(r0);
    __nv_bfloat16 l1 = __float2bfloat16_rn(r1);
    uint16_t uh0 = *(uint16_t*)&h0, uh1 = *(uint16_t*)&h1;
    uint16_t ul0 = *(uint16_t*)&l0, ul1 = *(uint16_t*)&l1;
    h = (uint32_t)uh0 | ((uint32_t)uh1 << 16);
    l = (uint32_t)ul0 | ((uint32_t)ul1 << 16);
}

__device__ __forceinline__ uint32_t packh2(float f0, float f1) {
    __half2 hh = __floats2half2_rn(f0, f1);
    return *(uint32_t*)&hh;
}

#define CP16(dst, src) \
    asm volatile("cp.async.cg.shared.global [%0], [%1], 16;" \
                 :: "r"(dst), "l"(src) : "memory")
#define CP_COMMIT() asm volatile("cp.async.commit_group;" ::: "memory")
#define CP_WAIT(n)  asm volatile("cp.async.wait_group %0;" :: "n"(n) : "memory")

// ---------------------------------------------------------------------------
// Kernel 1: merged qkv with register-prefetch pipelining.
// Grid 128, 512 thr = 16 warps (4 m x 4 n). Tile 128 x 192, K chunks of 32.
// ---------------------------------------------------------------------------
__global__ __launch_bounds__(512) void qkv_kernel(const float* __restrict__ x,
                                                  const float* __restrict__ Wq,
                                                  const float* __restrict__ Wk,
                                                  const float* __restrict__ Wv) {
    extern __shared__ __align__(16) char ds[];
    const uint32_t xh_b = smem_u32(ds);
    const uint32_t xl_b = xh_b + 10240, wh_b = xh_b + 20480, wl_b = xh_b + 35840;

    const int tid = threadIdx.x, wid = tid >> 5, lane = tid & 31;
    const int wm = wid >> 2, wn = wid & 3;
    const int m0 = blockIdx.x * 128;

    float4 px[2], pw[3];
    #pragma unroll
    for (int it = 0; it < 2; it++) {
        int i = tid + it * 512, r = i >> 3, f4 = i & 7;
        px[it] = *(const float4*)&x[(size_t)(m0 + r) * CC + f4 * 4];
    }
    #pragma unroll
    for (int it = 0; it < 3; it++) {
        int i = tid + it * 512, r = i >> 3, f4 = i & 7;
        const float* Wp = (r < 64) ? Wq : (r < 128) ? Wk : Wv;
        pw[it] = *(const float4*)&Wp[(size_t)(r & 63) * CC + f4 * 4];
    }

    float acc[2][6][4] = {};

    for (int c0 = 0; c0 < CC; c0 += 32) {
        #pragma unroll
        for (int it = 0; it < 2; it++) {
            int i = tid + it * 512, r = i >> 3, f4 = i & 7;
            uint32_t h0, l0, h1, l1;
            split2(px[it].x, px[it].y, h0, l0);
            split2(px[it].z, px[it].w, h1, l1);
            uint32_t o = (uint32_t)r * 80 + f4 * 8;
            *(uint32_t*)(ds + o)         = h0; *(uint32_t*)(ds + o + 4)         = h1;
            *(uint32_t*)(ds + 10240 + o) = l0; *(uint32_t*)(ds + 10240 + o + 4) = l1;
        }
        #pragma unroll
        for (int it = 0; it < 3; it++) {
            int i = tid + it * 512, r = i >> 3, f4 = i & 7;
            uint32_t h0, l0, h1, l1;
            split2(pw[it].x, pw[it].y, h0, l0);
            split2(pw[it].z, pw[it].w, h1, l1);
            uint32_t o = (uint32_t)r * 80 + f4 * 8;
            *(uint32_t*)(ds + 20480 + o) = h0; *(uint32_t*)(ds + 20480 + o + 4) = h1;
            *(uint32_t*)(ds + 35840 + o) = l0; *(uint32_t*)(ds + 35840 + o + 4) = l1;
        }
        __syncthreads();

        if (c0 + 32 < CC) {
            const int cn = c0 + 32;
            #pragma unroll
            for (int it = 0; it < 2; it++) {
                int i = tid + it * 512, r = i >> 3, f4 = i & 7;
                px[it] = *(const float4*)&x[(size_t)(m0 + r) * CC + cn + f4 * 4];
            }
            #pragma unroll
            for (int it = 0; it < 3; it++) {
                int i = tid + it * 512, r = i >> 3, f4 = i & 7;
                const float* Wp = (r < 64) ? Wq : (r < 128) ? Wk : Wv;
                pw[it] = *(const float4*)&Wp[(size_t)(r & 63) * CC + cn + f4 * 4];
            }
        }

        #pragma unroll
        for (int j = 0; j < 2; j++) {
            uint32_t ah[2][4], al[2][4];
            #pragma unroll
            for (int mt = 0; mt < 2; mt++) {
                uint32_t ro = (uint32_t)(wm * 32 + mt * 16 + (lane & 15)) * 80
                            + j * 32 + (lane >> 4) * 16;
                ldsm4(ah[mt], xh_b + ro);
                ldsm4(al[mt], xl_b + ro);
            }
            uint32_t bh[3][4], bl[3][4];
            #pragma unroll
            for (int n16 = 0; n16 < 3; n16++) {
                uint32_t ro = (uint32_t)(wn * 48 + n16 * 16 + (lane & 7)
                            + ((lane >> 4) & 1) * 8) * 80
                            + ((lane >> 3) & 1) * 16 + j * 32;
                ldsm4(bh[n16], wh_b + ro);
                ldsm4(bl[n16], wl_b + ro);
            }
            #pragma unroll
            for (int mt = 0; mt < 2; mt++)
                #pragma unroll
                for (int nt = 0; nt < 6; nt++) {
                    int n16 = nt >> 1, o = (nt & 1) * 2;
                    mma_bb(acc[mt][nt], ah[mt], bh[n16][o], bh[n16][o + 1]);
                    mma_bb(acc[mt][nt], ah[mt], bl[n16][o], bl[n16][o + 1]);
                    mma_bb(acc[mt][nt], al[mt], bh[n16][o], bh[n16][o + 1]);
                }
        }
        __syncthreads();
    }

    #pragma unroll
    for (int mt = 0; mt < 2; mt++)
        #pragma unroll
        for (int nt = 0; nt < 6; nt++) {
            int row0 = m0 + wm * 32 + mt * 16 + (lane >> 2);
            int cc = wn * 48 + nt * 8 + (lane & 3) * 2;
            if (cc < 128) {
                uint32_t* gh = (uint32_t*)((cc < 64) ? g_qh : g_kh);
                uint32_t* gl = (uint32_t*)((cc < 64) ? g_ql : g_kl);
                int col = cc & 63;
                uint32_t h, l;
                split2(acc[mt][nt][0], acc[mt][nt][1], h, l);
                gh[(size_t)row0 * 32 + (col >> 1)] = h;
                gl[(size_t)row0 * 32 + (col >> 1)] = l;
                split2(acc[mt][nt][2], acc[mt][nt][3], h, l);
                gh[(size_t)(row0 + 8) * 32 + (col >> 1)] = h;
                gl[(size_t)(row0 + 8) * 32 + (col >> 1)] = l;
            } else {
                int col = cc - 128;
                *(float2*)&g_v[(size_t)row0 * HH + col] =
                    make_float2(acc[mt][nt][0], acc[mt][nt][1]);
                *(float2*)&g_v[(size_t)(row0 + 8) * HH + col] =
                    make_float2(acc[mt][nt][2], acc[mt][nt][3]);
            }
        }
}

// ---------------------------------------------------------------------------
// Kernel 2: zsum — scores + exp + per-tile COLUMN partial sums, no E store.
// Grid (16 tt, 16 st, 8 b) lower-tri. 256 thr = 8 warps (4 m x 2 n64).
// Column reduction fully in registers via shuffles.
// smem: QH 0 | QL 18432 | KH 36864 | KL 55296 | zsm 73728 (4x128 f32) = 75776
// ---------------------------------------------------------------------------
__global__ __launch_bounds__(256) void zsum_kernel() {
    const int tt = blockIdx.x, st = blockIdx.y, b = blockIdx.z;
    if (st > tt) return;
    extern __shared__ __align__(16) char ds[];
    const uint32_t qh_b = smem_u32(ds);
    const uint32_t ql_b = qh_b + 18432, kh_b = qh_b + 36864, kl_b = qh_b + 55296;
    const int tid = threadIdx.x, wid = tid >> 5, lane = tid & 31;
    const int wm = wid >> 1, wn = wid & 1;
    const int t0 = tt * 128, s0 = st * 128;

    const uint32_t* qhg = (const uint32_t*)g_qh + ((size_t)b * TT + t0) * 32;
    const uint32_t* qlg = (const uint32_t*)g_ql + ((size_t)b * TT + t0) * 32;
    const uint32_t* khg = (const uint32_t*)g_kh + ((size_t)b * TT + s0) * 32;
    const uint32_t* klg = (const uint32_t*)g_kl + ((size_t)b * TT + s0) * 32;
    #pragma unroll
    for (int it = 0; it < 4; it++) {
        int i = tid + it * 256;               // 1024 uint4 per buffer
        int r = i >> 3, cg = i & 7;
        uint32_t o = (uint32_t)r * 144 + cg * 16;
        *(uint4*)(ds + o)         = *(const uint4*)(qhg + r * 32 + cg * 4);
        *(uint4*)(ds + 18432 + o) = *(const uint4*)(qlg + r * 32 + cg * 4);
        *(uint4*)(ds + 36864 + o) = *(const uint4*)(khg + r * 32 + cg * 4);
        *(uint4*)(ds + 55296 + o) = *(const uint4*)(klg + r * 32 + cg * 4);
    }
    __syncthreads();

    float acc[2][8][4] = {};
    #pragma unroll
    for (int j = 0; j < 4; j++) {
        uint32_t ah[2][4], al[2][4];
        #pragma unroll
        for (int mt = 0; mt < 2; mt++) {
            uint32_t ro = (uint32_t)(wm * 32 + mt * 16 + (lane & 15)) * 144
                        + j * 32 + (lane >> 4) * 16;
            ldsm4(ah[mt], qh_b + ro);
            ldsm4(al[mt], ql_b + ro);
        }
        uint32_t bh[4][4], bl[4][4];
        #pragma unroll
        for (int n16 = 0; n16 < 4; n16++) {
            uint32_t ro = (uint32_t)(wn * 64 + n16 * 16 + (lane & 7)
                        + ((lane >> 4) & 1) * 8) * 144
                        + ((lane >> 3) & 1) * 16 + j * 32;
            ldsm4(bh[n16], kh_b + ro);
            ldsm4(bl[n16], kl_b + ro);
        }
        #pragma unroll
        for (int mt = 0; mt < 2; mt++)
            #pragma unroll
            for (int nt = 0; nt < 8; nt++) {
                int n16 = nt >> 1, o = (nt & 1) * 2;
                mma_bb(acc[mt][nt], ah[mt], bh[n16][o], bh[n16][o + 1]);
                mma_bb(acc[mt][nt], ah[mt], bl[n16][o], bl[n16][o + 1]);
                mma_bb(acc[mt][nt], al[mt], bh[n16][o], bh[n16][o + 1]);
            }
    }

    // column partials: exp + mask, reduce over the warp's 32 rows via shuffles
    float* zsm = (float*)(ds + 73728);
    #pragma unroll
    for (int nt = 0; nt < 8; nt++) {
        float z0 = 0.f, z1 = 0.f;
        #pragma unroll
        for (int mt = 0; mt < 2; mt++) {
            int rA = t0 + wm * 32 + mt * 16 + (lane >> 2);
            int sc = s0 + wn * 64 + nt * 8 + (lane & 3) * 2;
            z0 += (sc <= rA)     ? __expf(acc[mt][nt][0] * SCALE) : 0.f;
            z0 += (sc <= rA + 8) ? __expf(acc[mt][nt][2] * SCALE) : 0.f;
            z1 += (sc + 1 <= rA)     ? __expf(acc[mt][nt][1] * SCALE) : 0.f;
            z1 += (sc + 1 <= rA + 8) ? __expf(acc[mt][nt][3] * SCALE) : 0.f;
        }
        z0 += __shfl_down_sync(0xffffffff, z0, 16);
        z0 += __shfl_down_sync(0xffffffff, z0, 8);
        z0 += __shfl_down_sync(0xffffffff, z0, 4);
        z1 += __shfl_down_sync(0xffffffff, z1, 16);
        z1 += __shfl_down_sync(0xffffffff, z1, 8);
        z1 += __shfl_down_sync(0xffffffff, z1, 4);
        if (lane < 4) {
            int col = wn * 64 + nt * 8 + lane * 2;
            zsm[wm * 128 + col]     = z0;
            zsm[wm * 128 + col + 1] = z1;
        }
    }
    __syncthreads();
    if (tid < 128) {
        float z = zsm[tid] + zsm[128 + tid] + zsm[256 + tid] + zsm[384 + tid];
        g_Zpart[((size_t)b * 16 + tt) * TT + s0 + tid] = z;
    }
}

// ---------------------------------------------------------------------------
// Kernel 3: Z_s, then v'[s] = v[s]/Z_s written transposed fp16 hi/lo [b][h][s].
// ---------------------------------------------------------------------------
__global__ __launch_bounds__(128) void colsum_kernel() {
    const int b = blockIdx.y;
    const int s = blockIdx.x * 128 + threadIdx.x;
    float z = 0.f;
    for (int tt = s >> 7; tt < 16; tt++)
        z += g_Zpart[((size_t)b * 16 + tt) * TT + s];
    const float inv = 1.0f / z;
    const float* vp = g_v + ((size_t)b * TT + s) * HH;
    __half* th = g_vTh + (size_t)b * HH * TT + s;
    __half* tl = g_vTl + (size_t)b * HH * TT + s;
    #pragma unroll
    for (int h4 = 0; h4 < HH; h4 += 4) {
        float4 vv = *(const float4*)&vp[h4];
        float f[4] = {vv.x * inv, vv.y * inv, vv.z * inv, vv.w * inv};
        #pragma unroll
        for (int j = 0; j < 4; j++) {
            __half hi = __float2half_rn(f[j]);
            __half lo = __float2half_rn(f[j] - __half2float(hi));
            th[(size_t)(h4 + j) * TT] = hi;
            tl[(size_t)(h4 + j) * TT] = lo;
        }
    }
}

// ---------------------------------------------------------------------------
// Kernel 4: fused out — recompute scores, exp in registers, P-fragment reuse
// as A of the PV MMA. Grid (16 tt, 2 split, 8 b), 256 thr (4 wm x 2 wn).
// 2-stage cp.async pipeline on k/v chunks (64 s each). atomicAdd x2 per elem.
// smem: QH 0 | QL 18432 | stage0 36864 | stage1 73728; total 110592
//   per stage: KH +0 (64x144B) | KL +9216 | VH +18432 | VL +27648
// ---------------------------------------------------------------------------
__global__ __launch_bounds__(256) void out_kernel(float* __restrict__ outp) {
    const int tt = blockIdx.x, split = blockIdx.y, b = blockIdx.z;
    const int t0 = tt * 128;
    const int nchunk = 2 * tt + 2;
    extern __shared__ __align__(16) char ds[];
    const uint32_t sb = smem_u32(ds);
    const int tid = threadIdx.x, wid = tid >> 5, lane = tid & 31;
    const int wm = wid >> 1, wn = wid & 1;

    // q tile (persistent)
    const uint32_t* qhg = (const uint32_t*)g_qh + ((size_t)b * TT + t0) * 32;
    const uint32_t* qlg = (const uint32_t*)g_ql + ((size_t)b * TT + t0) * 32;
    #pragma unroll
    for (int it = 0; it < 4; it++) {
        int i = tid + it * 256;
        int r = i >> 3, cg = i & 7;
        uint32_t o = (uint32_t)r * 144 + cg * 16;
        *(uint4*)(ds + o)         = *(const uint4*)(qhg + r * 32 + cg * 4);
        *(uint4*)(ds + 18432 + o) = *(const uint4*)(qlg + r * 32 + cg * 4);
    }

    const uint32_t* khg = (const uint32_t*)g_kh + (size_t)b * TT * 32;
    const uint32_t* klg = (const uint32_t*)g_kl + (size_t)b * TT * 32;
    const uint32_t* vhg = (const uint32_t*)g_vTh + (size_t)b * HH * 1024;
    const uint32_t* vlg = (const uint32_t*)g_vTl + (size_t)b * HH * 1024;

    auto issue = [&](int c, int buf) {
        const int s0 = c * 64;
        const uint32_t base = sb + 36864 + buf * 36864;
        #pragma unroll
        for (int it = 0; it < 2; it++) {
            int i = tid + it * 256;           // 512 rows-of-16B per buffer
            int r = i >> 3, cg = i & 7;
            uint32_t off = (uint32_t)r * 144 + cg * 16;
            CP16(base + off,         khg + (size_t)(s0 + r) * 32 + cg * 4);
            CP16(base + 9216 + off,  klg + (size_t)(s0 + r) * 32 + cg * 4);
            CP16(base + 18432 + off, vhg + (size_t)r * 1024 + (s0 >> 1) + cg * 4);
            CP16(base + 27648 + off, vlg + (size_t)r * 1024 + (s0 >> 1) + cg * 4);
        }
        CP_COMMIT();
    };

    float oacc[2][8][4] = {};
    issue(split, 0);
    int buf = 0;

    for (int c = split; c < nchunk; c += 2) {
        if (c + 2 < nchunk) { issue(c + 2, buf ^ 1); CP_WAIT(1); }
        else                { CP_WAIT(0); }
        __syncthreads();

        const uint32_t KB = sb + 36864 + buf * 36864;

        // -------- scores: 128t x 64s chunk; warp covers 32t x 32s ----------
        float sacc[2][4][4] = {};
        #pragma unroll
        for (int j = 0; j < 4; j++) {
            uint32_t ah[2][4], al[2][4];
            #pragma unroll
            for (int mt = 0; mt < 2; mt++) {
                uint32_t ro = (uint32_t)(wm * 32 + mt * 16 + (lane & 15)) * 144
                            + j * 32 + (lane >> 4) * 16;
                ldsm4(ah[mt], sb + ro);
                ldsm4(al[mt], sb + 18432 + ro);
            }
            uint32_t bh[2][4], bl[2][4];
            #pragma unroll
            for (int n16 = 0; n16 < 2; n16++) {
                uint32_t ro = (uint32_t)(wn * 32 + n16 * 16 + (lane & 7)
                            + ((lane >> 4) & 1) * 8) * 144
                            + ((lane >> 3) & 1) * 16 + j * 32;
                ldsm4(bh[n16], KB + ro);
                ldsm4(bl[n16], KB + 9216 + ro);
            }
            #pragma unroll
            for (int mt = 0; mt < 2; mt++)
                #pragma unroll
                for (int blk = 0; blk < 4; blk++) {
                    int n16 = blk >> 1, o = (blk & 1) * 2;
                    mma_bb(sacc[mt][blk], ah[mt], bh[n16][o], bh[n16][o + 1]);
                    mma_bb(sacc[mt][blk], ah[mt], bl[n16][o], bl[n16][o + 1]);
                    mma_bb(sacc[mt][blk], al[mt], bh[n16][o], bh[n16][o + 1]);
                }
        }

        // -------- exp + causal mask -> P fragments (A of PV mma) -----------
        uint32_t pa[2][2][4];
        #pragma unroll
        for (int mt = 0; mt < 2; mt++)
            #pragma unroll
            for (int blk = 0; blk < 4; blk++) {
                int rA = t0 + wm * 32 + mt * 16 + (lane >> 2);
                int sc = c * 64 + wn * 32 + blk * 8 + (lane & 3) * 2;
                float e0 = (sc     <= rA)     ? __expf(sacc[mt][blk][0] * SCALE) : 0.f;
                float e1 = (sc + 1 <= rA)     ? __expf(sacc[mt][blk][1] * SCALE) : 0.f;
                float e2 = (sc     <= rA + 8) ? __expf(sacc[mt][blk][2] * SCALE) : 0.f;
                float e3 = (sc + 1 <= rA + 8) ? __expf(sacc[mt][blk][3] * SCALE) : 0.f;
                int kk = blk >> 1;
                if ((blk & 1) == 0) {
                    pa[kk][mt][0] = packh2(e0, e1);
                    pa[kk][mt][1] = packh2(e2, e3);
                } else {
                    pa[kk][mt][2] = packh2(e0, e1);
                    pa[kk][mt][3] = packh2(e2, e3);
                }
            }

        // -------- PV: out += P (m32 x k32) @ v'^T (n64) --------------------
        #pragma unroll
        for (int kk = 0; kk < 2; kk++) {
            uint32_t bvh[4][4], bvl[4][4];
            #pragma unroll
            for (int n16 = 0; n16 < 4; n16++) {
                uint32_t ro = (uint32_t)(n16 * 16 + (lane & 7)
                            + ((lane >> 4) & 1) * 8) * 144
                            + ((lane >> 3) & 1) * 16 + wn * 64 + kk * 32;
                ldsm4(bvh[n16], KB + 18432 + ro);
                ldsm4(bvl[n16], KB + 27648 + ro);
            }
            #pragma unroll
            for (int mt = 0; mt < 2; mt++)
                #pragma unroll
                for (int nb = 0; nb < 8; nb++) {
                    int n16 = nb >> 1, o = (nb & 1) * 2;
                    mma_ff(oacc[mt][nb], pa[kk][mt], bvh[n16][o], bvh[n16][o + 1]);
                    mma_ff(oacc[mt][nb], pa[kk][mt], bvl[n16][o], bvl[n16][o + 1]);
                }
        }
        __syncthreads();
        buf ^= 1;
    }

    // -------- epilogue: reduce the two wn warps, then 2-way atomicAdd ------
    float* obuf = (float*)(ds + 36864);       // 128 x 68 f32 overlay
    if (wn == 0) {
        #pragma unroll
        for (int mt = 0; mt < 2; mt++)
            #pragma unroll
            for (int nb = 0; nb < 8; nb++) {
                int r0 = wm * 32 + mt * 16 + (lane >> 2);
                int cc = nb * 8 + (lane & 3) * 2;
                obuf[r0 * 68 + cc]           = oacc[mt][nb][0];
                obuf[r0 * 68 + cc + 1]       = oacc[mt][nb][1];
                obuf[(r0 + 8) * 68 + cc]     = oacc[mt][nb][2];
                obuf[(r0 + 8) * 68 + cc + 1] = oacc[mt][nb][3];
            }
    }
    __syncthreads();
    if (wn == 1) {
        #pragma unroll
        for (int mt = 0; mt < 2; mt++)
            #pragma unroll
            for (int nb = 0; nb < 8; nb++) {
                int r0 = wm * 32 + mt * 16 + (lane >> 2);
                int cc = nb * 8 + (lane & 3) * 2;
                obuf[r0 * 68 + cc]           += oacc[mt][nb][0];
                obuf[r0 * 68 + cc + 1]       += oacc[mt][nb][1];
                obuf[(r0 + 8) * 68 + cc]     += oacc[mt][nb][2];
                obuf[(r0 + 8) * 68 + cc + 1] += oacc[mt][nb][3];
            }
    }
    __syncthreads();
    #pragma unroll
    for (int it = 0; it < 32; it++) {
        int i = tid + it * 256;
        int r = i >> 6, cc = i & 63;
        atomicAdd(&outp[((size_t)b * TT + t0 + r) * HH + cc], obuf[r * 68 + cc]);
    }
}

// ---------------------------------------------------------------------------
extern "C" void kernel_launch(void* const* d_in, const int* in_sizes, int n_in,
                              void* d_out, int out_size) {
    const float* x  = (const float*)d_in[0];
    const float* Wq = (const float*)d_in[1];
    const float* Wk = (const float*)d_in[2];
    const float* Wv = (const float*)d_in[3];
    float* out = (float*)d_out;

    cudaFuncSetAttribute(qkv_kernel,  cudaFuncAttributeMaxDynamicSharedMemorySize, 51200);
    cudaFuncSetAttribute(zsum_kernel, cudaFuncAttributeMaxDynamicSharedMemorySize, 75776);
    cudaFuncSetAttribute(out_kernel,  cudaFuncAttributeMaxDynamicSharedMemorySize, 110592);

    cudaMemsetAsync(out, 0, (size_t)out_size * sizeof(float));
    qkv_kernel<<<(BB * TT) / 128, 512, 51200>>>(x, Wq, Wk, Wv);
    zsum_kernel<<<dim3(16, 16, BB), 256, 75776>>>();
    colsum_kernel<<<dim3(16, BB), 128>>>();
    out_kernel<<<dim3(16, 2, BB), 256, 110592>>>(out);
}

// round 14
// speedup vs baseline: 4.7554x; 1.3486x over previous
#include <cuda_runtime.h>
#include <cuda_bf16.h>
#include <cuda_fp16.h>
#include <cstdint>

#define BB 8
#define TT 2048
#define CC 1024
#define HH 64
#define SCALE 0.125f

// ---------------------------------------------------------------------------
// Device-global scratch (16B-aligned for uint4 / cp.async access)
// ---------------------------------------------------------------------------
__device__ __align__(16) __half g_qf[(size_t)BB * TT * HH];   // q fp16 [b][t][h]
__device__ __align__(16) __half g_kf[(size_t)BB * TT * HH];   // k fp16 [b][s][h]
__device__ __align__(16) float  g_v [(size_t)BB * TT * HH];   // v fp32 [b][s][h]
__device__ __align__(16) float  g_Zpart[(size_t)BB * 16 * TT];
__device__ __align__(16) __half g_vTf[(size_t)BB * HH * TT];  // v' fp16 [b][h][s]

// ---------------------------------------------------------------------------
// Helpers
// ---------------------------------------------------------------------------
__device__ __forceinline__ uint32_t smem_u32(const void* p) {
    uint32_t a;
    asm("{ .reg .u64 t; cvta.to.shared.u64 t, %1; cvt.u32.u64 %0, t; }"
        : "=r"(a) : "l"(p));
    return a;
}

__device__ __forceinline__ void ldsm4(uint32_t r[4], uint32_t addr) {
    asm volatile("ldmatrix.sync.aligned.m8n8.x4.shared.b16 {%0,%1,%2,%3}, [%4];"
                 : "=r"(r[0]), "=r"(r[1]), "=r"(r[2]), "=r"(r[3]) : "r"(addr));
}

__device__ __forceinline__ void mma_bb(float c[4], const uint32_t a[4],
                                       uint32_t b0, uint32_t b1) {
    asm volatile(
        "mma.sync.aligned.m16n8k16.row.col.f32.bf16.bf16.f32 "
        "{%0,%1,%2,%3}, {%4,%5,%6,%7}, {%8,%9}, {%0,%1,%2,%3};"
        : "+f"(c[0]), "+f"(c[1]), "+f"(c[2]), "+f"(c[3])
        : "r"(a[0]), "r"(a[1]), "r"(a[2]), "r"(a[3]), "r"(b0), "r"(b1));
}

__device__ __forceinline__ void mma_ff(float c[4], const uint32_t a[4],
                                       uint32_t b0, uint32_t b1) {
    asm volatile(
        "mma.sync.aligned.m16n8k16.row.col.f32.f16.f16.f32 "
        "{%0,%1,%2,%3}, {%4,%5,%6,%7}, {%8,%9}, {%0,%1,%2,%3};"
        : "+f"(c[0]), "+f"(c[1]), "+f"(c[2]), "+f"(c[3])
        : "r"(a[0]), "r"(a[1]), "r"(a[2]), "r"(a[3]), "r"(b0), "r"(b1));
}

__device__ __forceinline__ void split2(float f0, float f1, uint32_t& h, uint32_t& l) {
    __nv_bfloat16 h0 = __float2bfloat16_rn(f0);
    __nv_bfloat16 h1 = __float2bfloat16_rn(f1);
    float r0 = f0 - __bfloat162float(h0);
    float r1 = f1 - __bfloat162float(h1);
    __nv_bfloat16 l0 = __float2bfloat16_rn(r0);
    __nv_bfloat16 l1 = __float2bfloat16_rn(r1);
    uint16_t uh0 = *(uint16_t*)&h0, uh1 = *(uint16_t*)&h1;
    uint16_t ul0 = *(uint16_t*)&l0, ul1 = *(uint16_t*)&l1;
    h = (uint32_t)uh0 | ((uint32_t)uh1 << 16);
    l = (uint32_t)ul0 | ((uint32_t)ul1 << 16);
}

__device__ __forceinline__ uint32_t packh2(float f0, float f1) {
    __half2 hh = __floats2half2_rn(f0, f1);
    return *(uint32_t*)&hh;
}

#define CP16(dst, src) \
    asm volatile("cp.async.cg.shared.global [%0], [%1], 16;" \
                 :: "r"(dst), "l"(src) : "memory")
#define CP_COMMIT() asm volatile("cp.async.commit_group;" ::: "memory")
#define CP_WAIT(n)  asm volatile("cp.async.wait_group %0;" :: "n"(n) : "memory")

// ---------------------------------------------------------------------------
// Kernel 1: merged qkv (3-term split bf16, full precision).
// Grid 128, 512 thr = 16 warps (4 m x 4 n). Tile 128 x 192, K chunks of 32.
// Epilogue: q,k -> single fp16; v -> fp32.
// ---------------------------------------------------------------------------
__global__ __launch_bounds__(512) void qkv_kernel(const float* __restrict__ x,
                                                  const float* __restrict__ Wq,
                                                  const float* __restrict__ Wk,
                                                  const float* __restrict__ Wv) {
    extern __shared__ __align__(16) char ds[];
    const uint32_t xh_b = smem_u32(ds);
    const uint32_t xl_b = xh_b + 10240, wh_b = xh_b + 20480, wl_b = xh_b + 35840;

    const int tid = threadIdx.x, wid = tid >> 5, lane = tid & 31;
    const int wm = wid >> 2, wn = wid & 3;
    const int m0 = blockIdx.x * 128;

    float4 px[2], pw[3];
    #pragma unroll
    for (int it = 0; it < 2; it++) {
        int i = tid + it * 512, r = i >> 3, f4 = i & 7;
        px[it] = *(const float4*)&x[(size_t)(m0 + r) * CC + f4 * 4];
    }
    #pragma unroll
    for (int it = 0; it < 3; it++) {
        int i = tid + it * 512, r = i >> 3, f4 = i & 7;
        const float* Wp = (r < 64) ? Wq : (r < 128) ? Wk : Wv;
        pw[it] = *(const float4*)&Wp[(size_t)(r & 63) * CC + f4 * 4];
    }

    float acc[2][6][4] = {};

    for (int c0 = 0; c0 < CC; c0 += 32) {
        #pragma unroll
        for (int it = 0; it < 2; it++) {
            int i = tid + it * 512, r = i >> 3, f4 = i & 7;
            uint32_t h0, l0, h1, l1;
            split2(px[it].x, px[it].y, h0, l0);
            split2(px[it].z, px[it].w, h1, l1);
            uint32_t o = (uint32_t)r * 80 + f4 * 8;
            *(uint32_t*)(ds + o)         = h0; *(uint32_t*)(ds + o + 4)         = h1;
            *(uint32_t*)(ds + 10240 + o) = l0; *(uint32_t*)(ds + 10240 + o + 4) = l1;
        }
        #pragma unroll
        for (int it = 0; it < 3; it++) {
            int i = tid + it * 512, r = i >> 3, f4 = i & 7;
            uint32_t h0, l0, h1, l1;
            split2(pw[it].x, pw[it].y, h0, l0);
            split2(pw[it].z, pw[it].w, h1, l1);
            uint32_t o = (uint32_t)r * 80 + f4 * 8;
            *(uint32_t*)(ds + 20480 + o) = h0; *(uint32_t*)(ds + 20480 + o + 4) = h1;
            *(uint32_t*)(ds + 35840 + o) = l0; *(uint32_t*)(ds + 35840 + o + 4) = l1;
        }
        __syncthreads();

        if (c0 + 32 < CC) {
            const int cn = c0 + 32;
            #pragma unroll
            for (int it = 0; it < 2; it++) {
                int i = tid + it * 512, r = i >> 3, f4 = i & 7;
                px[it] = *(const float4*)&x[(size_t)(m0 + r) * CC + cn + f4 * 4];
            }
            #pragma unroll
            for (int it = 0; it < 3; it++) {
                int i = tid + it * 512, r = i >> 3, f4 = i & 7;
                const float* Wp = (r < 64) ? Wq : (r < 128) ? Wk : Wv;
                pw[it] = *(const float4*)&Wp[(size_t)(r & 63) * CC + cn + f4 * 4];
            }
        }

        #pragma unroll
        for (int j = 0; j < 2; j++) {
            uint32_t ah[2][4], al[2][4];
            #pragma unroll
            for (int mt = 0; mt < 2; mt++) {
                uint32_t ro = (uint32_t)(wm * 32 + mt * 16 + (lane & 15)) * 80
                            + j * 32 + (lane >> 4) * 16;
                ldsm4(ah[mt], xh_b + ro);
                ldsm4(al[mt], xl_b + ro);
            }
            uint32_t bh[3][4], bl[3][4];
            #pragma unroll
            for (int n16 = 0; n16 < 3; n16++) {
                uint32_t ro = (uint32_t)(wn * 48 + n16 * 16 + (lane & 7)
                            + ((lane >> 4) & 1) * 8) * 80
                            + ((lane >> 3) & 1) * 16 + j * 32;
                ldsm4(bh[n16], wh_b + ro);
                ldsm4(bl[n16], wl_b + ro);
            }
            #pragma unroll
            for (int mt = 0; mt < 2; mt++)
                #pragma unroll
                for (int nt = 0; nt < 6; nt++) {
                    int n16 = nt >> 1, o = (nt & 1) * 2;
                    mma_bb(acc[mt][nt], ah[mt], bh[n16][o], bh[n16][o + 1]);
                    mma_bb(acc[mt][nt], ah[mt], bl[n16][o], bl[n16][o + 1]);
                    mma_bb(acc[mt][nt], al[mt], bh[n16][o], bh[n16][o + 1]);
                }
        }
        __syncthreads();
    }

    #pragma unroll
    for (int mt = 0; mt < 2; mt++)
        #pragma unroll
        for (int nt = 0; nt < 6; nt++) {
            int row0 = m0 + wm * 32 + mt * 16 + (lane >> 2);
            int cc = wn * 48 + nt * 8 + (lane & 3) * 2;
            if (cc < 128) {
                uint32_t* gf = (uint32_t*)((cc < 64) ? g_qf : g_kf);
                int col = cc & 63;
                gf[(size_t)row0 * 32 + (col >> 1)] =
                    packh2(acc[mt][nt][0], acc[mt][nt][1]);
                gf[(size_t)(row0 + 8) * 32 + (col >> 1)] =
                    packh2(acc[mt][nt][2], acc[mt][nt][3]);
            } else {
                int col = cc - 128;
                *(float2*)&g_v[(size_t)row0 * HH + col] =
                    make_float2(acc[mt][nt][0], acc[mt][nt][1]);
                *(float2*)&g_v[(size_t)(row0 + 8) * HH + col] =
                    make_float2(acc[mt][nt][2], acc[mt][nt][3]);
            }
        }
}

// ---------------------------------------------------------------------------
// Kernel 2: zsum — fp16 scores (1 MMA) + exp + per-tile column partial sums.
// Grid (16 tt, 16 st, 8 b) lower-tri. 256 thr = 8 warps (4 m x 2 n64).
// smem: QF 0 (128x144B) | KF 18432 | zsm 36864 (512 f32) = 38912
// ---------------------------------------------------------------------------
__global__ __launch_bounds__(256) void zsum_kernel() {
    const int tt = blockIdx.x, st = blockIdx.y, b = blockIdx.z;
    if (st > tt) return;
    extern __shared__ __align__(16) char ds[];
    const uint32_t qf_b = smem_u32(ds);
    const uint32_t kf_b = qf_b + 18432;
    const int tid = threadIdx.x, wid = tid >> 5, lane = tid & 31;
    const int wm = wid >> 1, wn = wid & 1;
    const int t0 = tt * 128, s0 = st * 128;

    const uint32_t* qfg = (const uint32_t*)g_qf + ((size_t)b * TT + t0) * 32;
    const uint32_t* kfg = (const uint32_t*)g_kf + ((size_t)b * TT + s0) * 32;
    #pragma unroll
    for (int it = 0; it < 4; it++) {
        int i = tid + it * 256;               // 1024 uint4 per buffer
        int r = i >> 3, cg = i & 7;
        uint32_t o = (uint32_t)r * 144 + cg * 16;
        *(uint4*)(ds + o)         = *(const uint4*)(qfg + r * 32 + cg * 4);
        *(uint4*)(ds + 18432 + o) = *(const uint4*)(kfg + r * 32 + cg * 4);
    }
    __syncthreads();

    float acc[2][8][4] = {};
    #pragma unroll
    for (int j = 0; j < 4; j++) {
        uint32_t af[2][4];
        #pragma unroll
        for (int mt = 0; mt < 2; mt++) {
            uint32_t ro = (uint32_t)(wm * 32 + mt * 16 + (lane & 15)) * 144
                        + j * 32 + (lane >> 4) * 16;
            ldsm4(af[mt], qf_b + ro);
        }
        uint32_t bf[4][4];
        #pragma unroll
        for (int n16 = 0; n16 < 4; n16++) {
            uint32_t ro = (uint32_t)(wn * 64 + n16 * 16 + (lane & 7)
                        + ((lane >> 4) & 1) * 8) * 144
                        + ((lane >> 3) & 1) * 16 + j * 32;
            ldsm4(bf[n16], kf_b + ro);
        }
        #pragma unroll
        for (int mt = 0; mt < 2; mt++)
            #pragma unroll
            for (int nt = 0; nt < 8; nt++) {
                int n16 = nt >> 1, o = (nt & 1) * 2;
                mma_ff(acc[mt][nt], af[mt], bf[n16][o], bf[n16][o + 1]);
            }
    }

    // column partials: exp + mask, reduce over the warp's 32 rows via shuffles
    float* zsm = (float*)(ds + 36864);
    #pragma unroll
    for (int nt = 0; nt < 8; nt++) {
        float z0 = 0.f, z1 = 0.f;
        #pragma unroll
        for (int mt = 0; mt < 2; mt++) {
            int rA = t0 + wm * 32 + mt * 16 + (lane >> 2);
            int sc = s0 + wn * 64 + nt * 8 + (lane & 3) * 2;
            z0 += (sc <= rA)     ? __expf(acc[mt][nt][0] * SCALE) : 0.f;
            z0 += (sc <= rA + 8) ? __expf(acc[mt][nt][2] * SCALE) : 0.f;
            z1 += (sc + 1 <= rA)     ? __expf(acc[mt][nt][1] * SCALE) : 0.f;
            z1 += (sc + 1 <= rA + 8) ? __expf(acc[mt][nt][3] * SCALE) : 0.f;
        }
        z0 += __shfl_down_sync(0xffffffff, z0, 16);
        z0 += __shfl_down_sync(0xffffffff, z0, 8);
        z0 += __shfl_down_sync(0xffffffff, z0, 4);
        z1 += __shfl_down_sync(0xffffffff, z1, 16);
        z1 += __shfl_down_sync(0xffffffff, z1, 8);
        z1 += __shfl_down_sync(0xffffffff, z1, 4);
        if (lane < 4) {
            int col = wn * 64 + nt * 8 + lane * 2;
            zsm[wm * 128 + col]     = z0;
            zsm[wm * 128 + col + 1] = z1;
        }
    }
    __syncthreads();
    if (tid < 128) {
        float z = zsm[tid] + zsm[128 + tid] + zsm[256 + tid] + zsm[384 + tid];
        g_Zpart[((size_t)b * 16 + tt) * TT + s0 + tid] = z;
    }
}

// ---------------------------------------------------------------------------
// Kernel 3: Z_s, then v'[s] = v[s]/Z_s written transposed fp16 [b][h][s].
// ---------------------------------------------------------------------------
__global__ __launch_bounds__(128) void colsum_kernel() {
    const int b = blockIdx.y;
    const int s = blockIdx.x * 128 + threadIdx.x;
    float z = 0.f;
    for (int tt = s >> 7; tt < 16; tt++)
        z += g_Zpart[((size_t)b * 16 + tt) * TT + s];
    const float inv = 1.0f / z;
    const float* vp = g_v + ((size_t)b * TT + s) * HH;
    __half* tf = g_vTf + (size_t)b * HH * TT + s;
    #pragma unroll
    for (int h4 = 0; h4 < HH; h4 += 4) {
        float4 vv = *(const float4*)&vp[h4];
        tf[(size_t)(h4 + 0) * TT] = __float2half_rn(vv.x * inv);
        tf[(size_t)(h4 + 1) * TT] = __float2half_rn(vv.y * inv);
        tf[(size_t)(h4 + 2) * TT] = __float2half_rn(vv.z * inv);
        tf[(size_t)(h4 + 3) * TT] = __float2half_rn(vv.w * inv);
    }
}

// ---------------------------------------------------------------------------
// Kernel 4: fused out — fp16 scores (1 MMA) + exp + fp16 PV (1 MMA).
// Grid (16 tt, 2 split, 8 b), 256 thr (4 wm x 2 wn).
// 2-stage cp.async pipeline; atomicAdd x2 per element (deterministic).
// smem: QF 0 (18432) | stage0 18432 | stage1 36864; total 55296
//   per stage: KF +0 (64x144B = 9216) | VF +9216 (64x144B)
// ---------------------------------------------------------------------------
__global__ __launch_bounds__(256) void out_kernel(float* __restrict__ outp) {
    const int tt = blockIdx.x, split = blockIdx.y, b = blockIdx.z;
    const int t0 = tt * 128;
    const int nchunk = 2 * tt + 2;
    extern __shared__ __align__(16) char ds[];
    const uint32_t sb = smem_u32(ds);
    const int tid = threadIdx.x, wid = tid >> 5, lane = tid & 31;
    const int wm = wid >> 1, wn = wid & 1;

    // q tile (persistent, fp16)
    const uint32_t* qfg = (const uint32_t*)g_qf + ((size_t)b * TT + t0) * 32;
    #pragma unroll
    for (int it = 0; it < 4; it++) {
        int i = tid + it * 256;
        int r = i >> 3, cg = i & 7;
        *(uint4*)(ds + (uint32_t)r * 144 + cg * 16) =
            *(const uint4*)(qfg + r * 32 + cg * 4);
    }

    const uint32_t* kfg = (const uint32_t*)g_kf + (size_t)b * TT * 32;
    const uint32_t* vfg = (const uint32_t*)g_vTf + (size_t)b * HH * 1024;

    auto issue = [&](int c, int buf) {
        const int s0 = c * 64;
        const uint32_t base = sb + 18432 + buf * 18432;
        #pragma unroll
        for (int it = 0; it < 2; it++) {
            int i = tid + it * 256;           // 512 rows-of-16B per operand
            int r = i >> 3, cg = i & 7;
            uint32_t off = (uint32_t)r * 144 + cg * 16;
            CP16(base + off,        kfg + (size_t)(s0 + r) * 32 + cg * 4);
            CP16(base + 9216 + off, vfg + (size_t)r * 1024 + (s0 >> 1) + cg * 4);
        }
        CP_COMMIT();
    };

    float oacc[2][8][4] = {};
    issue(split, 0);
    int buf = 0;

    for (int c = split; c < nchunk; c += 2) {
        if (c + 2 < nchunk) { issue(c + 2, buf ^ 1); CP_WAIT(1); }
        else                { CP_WAIT(0); }
        __syncthreads();

        const uint32_t KB = sb + 18432 + buf * 18432;

        // -------- scores: 128t x 64s chunk; warp covers 32t x 32s ----------
        float sacc[2][4][4] = {};
        #pragma unroll
        for (int j = 0; j < 4; j++) {
            uint32_t af[2][4];
            #pragma unroll
            for (int mt = 0; mt < 2; mt++) {
                uint32_t ro = (uint32_t)(wm * 32 + mt * 16 + (lane & 15)) * 144
                            + j * 32 + (lane >> 4) * 16;
                ldsm4(af[mt], sb + ro);
            }
            uint32_t bf[2][4];
            #pragma unroll
            for (int n16 = 0; n16 < 2; n16++) {
                uint32_t ro = (uint32_t)(wn * 32 + n16 * 16 + (lane & 7)
                            + ((lane >> 4) & 1) * 8) * 144
                            + ((lane >> 3) & 1) * 16 + j * 32;
                ldsm4(bf[n16], KB + ro);
            }
            #pragma unroll
            for (int mt = 0; mt < 2; mt++)
                #pragma unroll
                for (int blk = 0; blk < 4; blk++) {
                    int n16 = blk >> 1, o = (blk & 1) * 2;
                    mma_ff(sacc[mt][blk], af[mt], bf[n16][o], bf[n16][o + 1]);
                }
        }

        // -------- exp + causal mask -> P fragments (A of PV mma) -----------
        uint32_t pa[2][2][4];
        #pragma unroll
        for (int mt = 0; mt < 2; mt++)
            #pragma unroll
            for (int blk = 0; blk < 4; blk++) {
                int rA = t0 + wm * 32 + mt * 16 + (lane >> 2);
                int sc = c * 64 + wn * 32 + blk * 8 + (lane & 3) * 2;
                float e0 = (sc     <= rA)     ? __expf(sacc[mt][blk][0] * SCALE) : 0.f;
                float e1 = (sc + 1 <= rA)     ? __expf(sacc[mt][blk][1] * SCALE) : 0.f;
                float e2 = (sc     <= rA + 8) ? __expf(sacc[mt][blk][2] * SCALE) : 0.f;
                float e3 = (sc + 1 <= rA + 8) ? __expf(sacc[mt][blk][3] * SCALE) : 0.f;
                int kk = blk >> 1;
                if ((blk & 1) == 0) {
                    pa[kk][mt][0] = packh2(e0, e1);
                    pa[kk][mt][1] = packh2(e2, e3);
                } else {
                    pa[kk][mt][2] = packh2(e0, e1);
                    pa[kk][mt][3] = packh2(e2, e3);
                }
            }

        // -------- PV: out += P (m32 x k32) @ v'^T (n64) --------------------
        #pragma unroll
        for (int kk = 0; kk < 2; kk++) {
            uint32_t bvf[4][4];
            #pragma unroll
            for (int n16 = 0; n16 < 4; n16++) {
                uint32_t ro = (uint32_t)(n16 * 16 + (lane & 7)
                            + ((lane >> 4) & 1) * 8) * 144
                            + ((lane >> 3) & 1) * 16 + wn * 64 + kk * 32;
                ldsm4(bvf[n16], KB + 9216 + ro);
            }
            #pragma unroll
            for (int mt = 0; mt < 2; mt++)
                #pragma unroll
                for (int nb = 0; nb < 8; nb++) {
                    int n16 = nb >> 1, o = (nb & 1) * 2;
                    mma_ff(oacc[mt][nb], pa[kk][mt], bvf[n16][o], bvf[n16][o + 1]);
                }
        }
        __syncthreads();
        buf ^= 1;
    }

    // -------- epilogue: reduce the two wn warps, then 2-way atomicAdd ------
    float* obuf = (float*)(ds + 18432);       // 128 x 68 f32 overlay
    if (wn == 0) {
        #pragma unroll
        for (int mt = 0; mt < 2; mt++)
            #pragma unroll
            for (int nb = 0; nb < 8; nb++) {
                int r0 = wm * 32 + mt * 16 + (lane >> 2);
                int cc = nb * 8 + (lane & 3) * 2;
                obuf[r0 * 68 + cc]           = oacc[mt][nb][0];
                obuf[r0 * 68 + cc + 1]       = oacc[mt][nb][1];
                obuf[(r0 + 8) * 68 + cc]     = oacc[mt][nb][2];
                obuf[(r0 + 8) * 68 + cc + 1] = oacc[mt][nb][3];
            }
    }
    __syncthreads();
    if (wn == 1) {
        #pragma unroll
        for (int mt = 0; mt < 2; mt++)
            #pragma unroll
            for (int nb = 0; nb < 8; nb++) {
                int r0 = wm * 32 + mt * 16 + (lane >> 2);
                int cc = nb * 8 + (lane & 3) * 2;
                obuf[r0 * 68 + cc]           += oacc[mt][nb][0];
                obuf[r0 * 68 + cc + 1]       += oacc[mt][nb][1];
                obuf[(r0 + 8) * 68 + cc]     += oacc[mt][nb][2];
                obuf[(r0 + 8) * 68 + cc + 1] += oacc[mt][nb][3];
            }
    }
    __syncthreads();
    #pragma unroll
    for (int it = 0; it < 32; it++) {
        int i = tid + it * 256;
        int r = i >> 6, cc = i & 63;
        atomicAdd(&outp[((size_t)b * TT + t0 + r) * HH + cc], obuf[r * 68 + cc]);
    }
}

// ---------------------------------------------------------------------------
extern "C" void kernel_launch(void* const* d_in, const int* in_sizes, int n_in,
                              void* d_out, int out_size) {
    const float* x  = (const float*)d_in[0];
    const float* Wq = (const float*)d_in[1];
    const float* Wk = (const float*)d_in[2];
    const float* Wv = (const float*)d_in[3];
    float* out = (float*)d_out;

    cudaFuncSetAttribute(qkv_kernel,  cudaFuncAttributeMaxDynamicSharedMemorySize, 51200);
    cudaFuncSetAttribute(zsum_kernel, cudaFuncAttributeMaxDynamicSharedMemorySize, 38912);
    cudaFuncSetAttribute(out_kernel,  cudaFuncAttributeMaxDynamicSharedMemorySize, 55296);

    cudaMemsetAsync(out, 0, (size_t)out_size * sizeof(float));
    qkv_kernel<<<(BB * TT) / 128, 512, 51200>>>(x, Wq, Wk, Wv);
    zsum_kernel<<<dim3(16, 16, BB), 256, 38912>>>();
    colsum_kernel<<<dim3(16, BB), 128>>>();
    out_kernel<<<dim3(16, 2, BB), 256, 55296>>>(out);
}

// round 15
// speedup vs baseline: 7.8575x; 1.6523x over previous
#include <cuda_runtime.h>
#include <cuda_bf16.h>
#include <cuda_fp16.h>
#include <cstdint>

#define BB 8
#define TT 2048
#define CC 1024
#define HH 64
#define SCALE 0.125f

// ---------------------------------------------------------------------------
// Device-global scratch (16B-aligned for uint4 / cp.async access)
// ---------------------------------------------------------------------------
__device__ __align__(16) __half g_qf[(size_t)BB * TT * HH];   // q fp16 [b][t][h]
__device__ __align__(16) __half g_kf[(size_t)BB * TT * HH];   // k fp16 [b][s][h]
__device__ __align__(16) float  g_v [(size_t)BB * TT * HH];   // v fp32 [b][s][h]
__device__ __align__(16) float  g_Zpart[(size_t)BB * 16 * TT];
__device__ __align__(16) __half g_vTf[(size_t)BB * HH * TT];  // v' fp16 [b][h][s]

// ---------------------------------------------------------------------------
// Helpers
// ---------------------------------------------------------------------------
__device__ __forceinline__ uint32_t smem_u32(const void* p) {
    uint32_t a;
    asm("{ .reg .u64 t; cvta.to.shared.u64 t, %1; cvt.u32.u64 %0, t; }"
        : "=r"(a) : "l"(p));
    return a;
}

__device__ __forceinline__ void ldsm4(uint32_t r[4], uint32_t addr) {
    asm volatile("ldmatrix.sync.aligned.m8n8.x4.shared.b16 {%0,%1,%2,%3}, [%4];"
                 : "=r"(r[0]), "=r"(r[1]), "=r"(r[2]), "=r"(r[3]) : "r"(addr));
}

__device__ __forceinline__ void mma_ff(float c[4], const uint32_t a[4],
                                       uint32_t b0, uint32_t b1) {
    asm volatile(
        "mma.sync.aligned.m16n8k16.row.col.f32.f16.f16.f32 "
        "{%0,%1,%2,%3}, {%4,%5,%6,%7}, {%8,%9}, {%0,%1,%2,%3};"
        : "+f"(c[0]), "+f"(c[1]), "+f"(c[2]), "+f"(c[3])
        : "r"(a[0]), "r"(a[1]), "r"(a[2]), "r"(a[3]), "r"(b0), "r"(b1));
}

__device__ __forceinline__ uint32_t packh2(float f0, float f1) {
    __half2 hh = __floats2half2_rn(f0, f1);
    return *(uint32_t*)&hh;
}

#define CP16(dst, src) \
    asm volatile("cp.async.cg.shared.global [%0], [%1], 16;" \
                 :: "r"(dst), "l"(src) : "memory")
#define CP_COMMIT() asm volatile("cp.async.commit_group;" ::: "memory")
#define CP_WAIT(n)  asm volatile("cp.async.wait_group %0;" :: "n"(n) : "memory")

// ---------------------------------------------------------------------------
// Kernel 1: merged qkv, single fp16 MMA. Grid 128, 512 thr = 16 warps
// (4 m x 4 n). Tile 128 x 192, K chunks of 32. Register-prefetch pipelining.
// smem: X [128 x 80B] = 10240 | W [192 x 80B] = 15360; total 25600
// ---------------------------------------------------------------------------
__global__ __launch_bounds__(512) void qkv_kernel(const float* __restrict__ x,
                                                  const float* __restrict__ Wq,
                                                  const float* __restrict__ Wk,
                                                  const float* __restrict__ Wv) {
    extern __shared__ __align__(16) char ds[];
    const uint32_t xb = smem_u32(ds);
    const uint32_t wb = xb + 10240;

    const int tid = threadIdx.x, wid = tid >> 5, lane = tid & 31;
    const int wm = wid >> 2, wn = wid & 3;
    const int m0 = blockIdx.x * 128;

    float4 px[2], pw[3];
    #pragma unroll
    for (int it = 0; it < 2; it++) {
        int i = tid + it * 512, r = i >> 3, f4 = i & 7;
        px[it] = *(const float4*)&x[(size_t)(m0 + r) * CC + f4 * 4];
    }
    #pragma unroll
    for (int it = 0; it < 3; it++) {
        int i = tid + it * 512, r = i >> 3, f4 = i & 7;
        const float* Wp = (r < 64) ? Wq : (r < 128) ? Wk : Wv;
        pw[it] = *(const float4*)&Wp[(size_t)(r & 63) * CC + f4 * 4];
    }

    float acc[2][6][4] = {};

    for (int c0 = 0; c0 < CC; c0 += 32) {
        #pragma unroll
        for (int it = 0; it < 2; it++) {
            int i = tid + it * 512, r = i >> 3, f4 = i & 7;
            uint32_t o = (uint32_t)r * 80 + f4 * 8;
            *(uint32_t*)(ds + o)     = packh2(px[it].x, px[it].y);
            *(uint32_t*)(ds + o + 4) = packh2(px[it].z, px[it].w);
        }
        #pragma unroll
        for (int it = 0; it < 3; it++) {
            int i = tid + it * 512, r = i >> 3, f4 = i & 7;
            uint32_t o = 10240 + (uint32_t)r * 80 + f4 * 8;
            *(uint32_t*)(ds + o)     = packh2(pw[it].x, pw[it].y);
            *(uint32_t*)(ds + o + 4) = packh2(pw[it].z, pw[it].w);
        }
        __syncthreads();

        if (c0 + 32 < CC) {
            const int cn = c0 + 32;
            #pragma unroll
            for (int it = 0; it < 2; it++) {
                int i = tid + it * 512, r = i >> 3, f4 = i & 7;
                px[it] = *(const float4*)&x[(size_t)(m0 + r) * CC + cn + f4 * 4];
            }
            #pragma unroll
            for (int it = 0; it < 3; it++) {
                int i = tid + it * 512, r = i >> 3, f4 = i & 7;
                const float* Wp = (r < 64) ? Wq : (r < 128) ? Wk : Wv;
                pw[it] = *(const float4*)&Wp[(size_t)(r & 63) * CC + cn + f4 * 4];
            }
        }

        #pragma unroll
        for (int j = 0; j < 2; j++) {
            uint32_t af[2][4];
            #pragma unroll
            for (int mt = 0; mt < 2; mt++) {
                uint32_t ro = (uint32_t)(wm * 32 + mt * 16 + (lane & 15)) * 80
                            + j * 32 + (lane >> 4) * 16;
                ldsm4(af[mt], xb + ro);
            }
            uint32_t bf[3][4];
            #pragma unroll
            for (int n16 = 0; n16 < 3; n16++) {
                uint32_t ro = (uint32_t)(wn * 48 + n16 * 16 + (lane & 7)
                            + ((lane >> 4) & 1) * 8) * 80
                            + ((lane >> 3) & 1) * 16 + j * 32;
                ldsm4(bf[n16], wb + ro);
            }
            #pragma unroll
            for (int mt = 0; mt < 2; mt++)
                #pragma unroll
                for (int nt = 0; nt < 6; nt++) {
                    int n16 = nt >> 1, o = (nt & 1) * 2;
                    mma_ff(acc[mt][nt], af[mt], bf[n16][o], bf[n16][o + 1]);
                }
        }
        __syncthreads();
    }

    #pragma unroll
    for (int mt = 0; mt < 2; mt++)
        #pragma unroll
        for (int nt = 0; nt < 6; nt++) {
            int row0 = m0 + wm * 32 + mt * 16 + (lane >> 2);
            int cc = wn * 48 + nt * 8 + (lane & 3) * 2;
            if (cc < 128) {
                uint32_t* gf = (uint32_t*)((cc < 64) ? g_qf : g_kf);
                int col = cc & 63;
                gf[(size_t)row0 * 32 + (col >> 1)] =
                    packh2(acc[mt][nt][0], acc[mt][nt][1]);
                gf[(size_t)(row0 + 8) * 32 + (col >> 1)] =
                    packh2(acc[mt][nt][2], acc[mt][nt][3]);
            } else {
                int col = cc - 128;
                *(float2*)&g_v[(size_t)row0 * HH + col] =
                    make_float2(acc[mt][nt][0], acc[mt][nt][1]);
                *(float2*)&g_v[(size_t)(row0 + 8) * HH + col] =
                    make_float2(acc[mt][nt][2], acc[mt][nt][3]);
            }
        }
}

// ---------------------------------------------------------------------------
// Kernel 2: zsum — fp16 scores (1 MMA) + exp + per-tile column partial sums.
// Grid (16 tt, 16 st, 8 b) lower-tri. 256 thr = 8 warps (4 m x 2 n64).
// smem: QF 0 (128x144B) | KF 18432 | zsm 36864 (512 f32) = 38912
// ---------------------------------------------------------------------------
__global__ __launch_bounds__(256) void zsum_kernel() {
    const int tt = blockIdx.x, st = blockIdx.y, b = blockIdx.z;
    if (st > tt) return;
    extern __shared__ __align__(16) char ds[];
    const uint32_t qf_b = smem_u32(ds);
    const uint32_t kf_b = qf_b + 18432;
    const int tid = threadIdx.x, wid = tid >> 5, lane = tid & 31;
    const int wm = wid >> 1, wn = wid & 1;
    const int t0 = tt * 128, s0 = st * 128;

    const uint32_t* qfg = (const uint32_t*)g_qf + ((size_t)b * TT + t0) * 32;
    const uint32_t* kfg = (const uint32_t*)g_kf + ((size_t)b * TT + s0) * 32;
    #pragma unroll
    for (int it = 0; it < 4; it++) {
        int i = tid + it * 256;
        int r = i >> 3, cg = i & 7;
        uint32_t o = (uint32_t)r * 144 + cg * 16;
        *(uint4*)(ds + o)         = *(const uint4*)(qfg + r * 32 + cg * 4);
        *(uint4*)(ds + 18432 + o) = *(const uint4*)(kfg + r * 32 + cg * 4);
    }
    __syncthreads();

    float acc[2][8][4] = {};
    #pragma unroll
    for (int j = 0; j < 4; j++) {
        uint32_t af[2][4];
        #pragma unroll
        for (int mt = 0; mt < 2; mt++) {
            uint32_t ro = (uint32_t)(wm * 32 + mt * 16 + (lane & 15)) * 144
                        + j * 32 + (lane >> 4) * 16;
            ldsm4(af[mt], qf_b + ro);
        }
        uint32_t bf[4][4];
        #pragma unroll
        for (int n16 = 0; n16 < 4; n16++) {
            uint32_t ro = (uint32_t)(wn * 64 + n16 * 16 + (lane & 7)
                        + ((lane >> 4) & 1) * 8) * 144
                        + ((lane >> 3) & 1) * 16 + j * 32;
            ldsm4(bf[n16], kf_b + ro);
        }
        #pragma unroll
        for (int mt = 0; mt < 2; mt++)
            #pragma unroll
            for (int nt = 0; nt < 8; nt++) {
                int n16 = nt >> 1, o = (nt & 1) * 2;
                mma_ff(acc[mt][nt], af[mt], bf[n16][o], bf[n16][o + 1]);
            }
    }

    // column partials: exp + mask, reduce over the warp's 32 rows via shuffles
    float* zsm = (float*)(ds + 36864);
    #pragma unroll
    for (int nt = 0; nt < 8; nt++) {
        float z0 = 0.f, z1 = 0.f;
        #pragma unroll
        for (int mt = 0; mt < 2; mt++) {
            int rA = t0 + wm * 32 + mt * 16 + (lane >> 2);
            int sc = s0 + wn * 64 + nt * 8 + (lane & 3) * 2;
            z0 += (sc <= rA)     ? __expf(acc[mt][nt][0] * SCALE) : 0.f;
            z0 += (sc <= rA + 8) ? __expf(acc[mt][nt][2] * SCALE) : 0.f;
            z1 += (sc + 1 <= rA)     ? __expf(acc[mt][nt][1] * SCALE) : 0.f;
            z1 += (sc + 1 <= rA + 8) ? __expf(acc[mt][nt][3] * SCALE) : 0.f;
        }
        z0 += __shfl_down_sync(0xffffffff, z0, 16);
        z0 += __shfl_down_sync(0xffffffff, z0, 8);
        z0 += __shfl_down_sync(0xffffffff, z0, 4);
        z1 += __shfl_down_sync(0xffffffff, z1, 16);
        z1 += __shfl_down_sync(0xffffffff, z1, 8);
        z1 += __shfl_down_sync(0xffffffff, z1, 4);
        if (lane < 4) {
            int col = wn * 64 + nt * 8 + lane * 2;
            zsm[wm * 128 + col]     = z0;
            zsm[wm * 128 + col + 1] = z1;
        }
    }
    __syncthreads();
    if (tid < 128) {
        float z = zsm[tid] + zsm[128 + tid] + zsm[256 + tid] + zsm[384 + tid];
        g_Zpart[((size_t)b * 16 + tt) * TT + s0 + tid] = z;
    }
}

// ---------------------------------------------------------------------------
// Kernel 3: Z_s, then v'[s] = v[s]/Z_s written transposed fp16 [b][h][s].
// ---------------------------------------------------------------------------
__global__ __launch_bounds__(128) void colsum_kernel() {
    const int b = blockIdx.y;
    const int s = blockIdx.x * 128 + threadIdx.x;
    float z = 0.f;
    for (int tt = s >> 7; tt < 16; tt++)
        z += g_Zpart[((size_t)b * 16 + tt) * TT + s];
    const float inv = 1.0f / z;
    const float* vp = g_v + ((size_t)b * TT + s) * HH;
    __half* tf = g_vTf + (size_t)b * HH * TT + s;
    #pragma unroll
    for (int h4 = 0; h4 < HH; h4 += 4) {
        float4 vv = *(const float4*)&vp[h4];
        tf[(size_t)(h4 + 0) * TT] = __float2half_rn(vv.x * inv);
        tf[(size_t)(h4 + 1) * TT] = __float2half_rn(vv.y * inv);
        tf[(size_t)(h4 + 2) * TT] = __float2half_rn(vv.z * inv);
        tf[(size_t)(h4 + 3) * TT] = __float2half_rn(vv.w * inv);
    }
}

// ---------------------------------------------------------------------------
// Kernel 4: fused out with TILE PAIRING for load balance.
// Grid (8 pair, 2 split, 8 b) = 128 CTAs; CTA pp handles tt = pp and 15-pp
// (17 chunks total, split 2 ways -> uniform ~8.5 chunks per CTA).
// 2-stage cp.async pipeline; atomicAdd x2 per element.
// smem: QF 0 (18432) | stage0 18432 | stage1 36864; total 55296
// ---------------------------------------------------------------------------
__global__ __launch_bounds__(256) void out_kernel(float* __restrict__ outp) {
    const int pp = blockIdx.x, split = blockIdx.y, b = blockIdx.z;
    extern __shared__ __align__(16) char ds[];
    const uint32_t sb = smem_u32(ds);
    const int tid = threadIdx.x, wid = tid >> 5, lane = tid & 31;
    const int wm = wid >> 1, wn = wid & 1;

    const uint32_t* kfg = (const uint32_t*)g_kf + (size_t)b * TT * 32;
    const uint32_t* vfg = (const uint32_t*)g_vTf + (size_t)b * HH * 1024;

    for (int half = 0; half < 2; half++) {
        const int tt = half ? (15 - pp) : pp;
        const int t0 = tt * 128;
        const int nchunk = 2 * tt + 2;
        if (half) __syncthreads();            // smem reuse fence between halves

        // q tile (fp16)
        const uint32_t* qfg = (const uint32_t*)g_qf + ((size_t)b * TT + t0) * 32;
        #pragma unroll
        for (int it = 0; it < 4; it++) {
            int i = tid + it * 256;
            int r = i >> 3, cg = i & 7;
            *(uint4*)(ds + (uint32_t)r * 144 + cg * 16) =
                *(const uint4*)(qfg + r * 32 + cg * 4);
        }

        auto issue = [&](int c, int buf) {
            const int s0 = c * 64;
            const uint32_t base = sb + 18432 + buf * 18432;
            #pragma unroll
            for (int it = 0; it < 2; it++) {
                int i = tid + it * 256;
                int r = i >> 3, cg = i & 7;
                uint32_t off = (uint32_t)r * 144 + cg * 16;
                CP16(base + off,        kfg + (size_t)(s0 + r) * 32 + cg * 4);
                CP16(base + 9216 + off, vfg + (size_t)r * 1024 + (s0 >> 1) + cg * 4);
            }
            CP_COMMIT();
        };

        float oacc[2][8][4] = {};
        issue(split, 0);
        int buf = 0;

        for (int c = split; c < nchunk; c += 2) {
            if (c + 2 < nchunk) { issue(c + 2, buf ^ 1); CP_WAIT(1); }
            else                { CP_WAIT(0); }
            __syncthreads();

            const uint32_t KB = sb + 18432 + buf * 18432;

            // ------ scores: 128t x 64s chunk; warp covers 32t x 32s --------
            float sacc[2][4][4] = {};
            #pragma unroll
            for (int j = 0; j < 4; j++) {
                uint32_t af[2][4];
                #pragma unroll
                for (int mt = 0; mt < 2; mt++) {
                    uint32_t ro = (uint32_t)(wm * 32 + mt * 16 + (lane & 15)) * 144
                                + j * 32 + (lane >> 4) * 16;
                    ldsm4(af[mt], sb + ro);
                }
                uint32_t bf[2][4];
                #pragma unroll
                for (int n16 = 0; n16 < 2; n16++) {
                    uint32_t ro = (uint32_t)(wn * 32 + n16 * 16 + (lane & 7)
                                + ((lane >> 4) & 1) * 8) * 144
                                + ((lane >> 3) & 1) * 16 + j * 32;
                    ldsm4(bf[n16], KB + ro);
                }
                #pragma unroll
                for (int mt = 0; mt < 2; mt++)
                    #pragma unroll
                    for (int blk = 0; blk < 4; blk++) {
                        int n16 = blk >> 1, o = (blk & 1) * 2;
                        mma_ff(sacc[mt][blk], af[mt], bf[n16][o], bf[n16][o + 1]);
                    }
            }

            // ------ exp + causal mask -> P fragments (A of PV mma) ---------
            uint32_t pa[2][2][4];
            #pragma unroll
            for (int mt = 0; mt < 2; mt++)
                #pragma unroll
                for (int blk = 0; blk < 4; blk++) {
                    int rA = t0 + wm * 32 + mt * 16 + (lane >> 2);
                    int sc = c * 64 + wn * 32 + blk * 8 + (lane & 3) * 2;
                    float e0 = (sc     <= rA)     ? __expf(sacc[mt][blk][0] * SCALE) : 0.f;
                    float e1 = (sc + 1 <= rA)     ? __expf(sacc[mt][blk][1] * SCALE) : 0.f;
                    float e2 = (sc     <= rA + 8) ? __expf(sacc[mt][blk][2] * SCALE) : 0.f;
                    float e3 = (sc + 1 <= rA + 8) ? __expf(sacc[mt][blk][3] * SCALE) : 0.f;
                    int kk = blk >> 1;
                    if ((blk & 1) == 0) {
                        pa[kk][mt][0] = packh2(e0, e1);
                        pa[kk][mt][1] = packh2(e2, e3);
                    } else {
                        pa[kk][mt][2] = packh2(e0, e1);
                        pa[kk][mt][3] = packh2(e2, e3);
                    }
                }

            // ------ PV: out += P (m32 x k32) @ v'^T (n64) ------------------
            #pragma unroll
            for (int kk = 0; kk < 2; kk++) {
                uint32_t bvf[4][4];
                #pragma unroll
                for (int n16 = 0; n16 < 4; n16++) {
                    uint32_t ro = (uint32_t)(n16 * 16 + (lane & 7)
                                + ((lane >> 4) & 1) * 8) * 144
                                + ((lane >> 3) & 1) * 16 + wn * 64 + kk * 32;
                    ldsm4(bvf[n16], KB + 9216 + ro);
                }
                #pragma unroll
                for (int mt = 0; mt < 2; mt++)
                    #pragma unroll
                    for (int nb = 0; nb < 8; nb++) {
                        int n16 = nb >> 1, o = (nb & 1) * 2;
                        mma_ff(oacc[mt][nb], pa[kk][mt], bvf[n16][o], bvf[n16][o + 1]);
                    }
            }
            __syncthreads();
            buf ^= 1;
        }

        // ------ epilogue: reduce the two wn warps, then 2-way atomicAdd ----
        float* obuf = (float*)(ds + 18432);   // 128 x 68 f32 overlay
        if (wn == 0) {
            #pragma unroll
            for (int mt = 0; mt < 2; mt++)
                #pragma unroll
                for (int nb = 0; nb < 8; nb++) {
                    int r0 = wm * 32 + mt * 16 + (lane >> 2);
                    int cc = nb * 8 + (lane & 3) * 2;
                    obuf[r0 * 68 + cc]           = oacc[mt][nb][0];
                    obuf[r0 * 68 + cc + 1]       = oacc[mt][nb][1];
                    obuf[(r0 + 8) * 68 + cc]     = oacc[mt][nb][2];
                    obuf[(r0 + 8) * 68 + cc + 1] = oacc[mt][nb][3];
                }
        }
        __syncthreads();
        if (wn == 1) {
            #pragma unroll
            for (int mt = 0; mt < 2; mt++)
                #pragma unroll
                for (int nb = 0; nb < 8; nb++) {
                    int r0 = wm * 32 + mt * 16 + (lane >> 2);
                    int cc = nb * 8 + (lane & 3) * 2;
                    obuf[r0 * 68 + cc]           += oacc[mt][nb][0];
                    obuf[r0 * 68 + cc + 1]       += oacc[mt][nb][1];
                    obuf[(r0 + 8) * 68 + cc]     += oacc[mt][nb][2];
                    obuf[(r0 + 8) * 68 + cc + 1] += oacc[mt][nb][3];
                }
        }
        __syncthreads();
        #pragma unroll
        for (int it = 0; it < 32; it++) {
            int i = tid + it * 256;
            int r = i >> 6, cc = i & 63;
            atomicAdd(&outp[((size_t)b * TT + t0 + r) * HH + cc], obuf[r * 68 + cc]);
        }
    }
}

// ---------------------------------------------------------------------------
extern "C" void kernel_launch(void* const* d_in, const int* in_sizes, int n_in,
                              void* d_out, int out_size) {
    const float* x  = (const float*)d_in[0];
    const float* Wq = (const float*)d_in[1];
    const float* Wk = (const float*)d_in[2];
    const float* Wv = (const float*)d_in[3];
    float* out = (float*)d_out;

    cudaFuncSetAttribute(qkv_kernel,  cudaFuncAttributeMaxDynamicSharedMemorySize, 25600);
    cudaFuncSetAttribute(zsum_kernel, cudaFuncAttributeMaxDynamicSharedMemorySize, 38912);
    cudaFuncSetAttribute(out_kernel,  cudaFuncAttributeMaxDynamicSharedMemorySize, 55296);

    cudaMemsetAsync(out, 0, (size_t)out_size * sizeof(float));
    qkv_kernel<<<(BB * TT) / 128, 512, 25600>>>(x, Wq, Wk, Wv);
    zsum_kernel<<<dim3(16, 16, BB), 256, 38912>>>();
    colsum_kernel<<<dim3(16, BB), 128>>>();
    out_kernel<<<dim3(8, 2, BB), 256, 55296>>>(out);
}

// round 17
// speedup vs baseline: 7.8860x; 1.0036x over previous
#include <cuda_runtime.h>
#include <cuda_bf16.h>
#include <cuda_fp16.h>
#include <cstdint>

#define BB 8
#define TT 2048
#define CC 1024
#define HH 64
#define SCALE 0.125f

// ---------------------------------------------------------------------------
// Device-global scratch (16B-aligned for uint4 / cp.async access)
// ---------------------------------------------------------------------------
__device__ __align__(16) __half g_qf[(size_t)BB * TT * HH];   // q fp16 [b][t][h]
__device__ __align__(16) __half g_kf[(size_t)BB * TT * HH];   // k fp16 [b][s][h]
__device__ __align__(16) float  g_v [(size_t)BB * TT * HH];   // v fp32 [b][s][h]
__device__ __align__(16) float  g_Zpart[(size_t)BB * 16 * TT];
__device__ __align__(16) __half g_vTf[(size_t)BB * HH * TT];  // v' fp16 [b][h][s]

// ---------------------------------------------------------------------------
// Helpers
// ---------------------------------------------------------------------------
__device__ __forceinline__ uint32_t smem_u32(const void* p) {
    uint32_t a;
    asm("{ .reg .u64 t; cvta.to.shared.u64 t, %1; cvt.u32.u64 %0, t; }"
        : "=r"(a) : "l"(p));
    return a;
}

__device__ __forceinline__ void ldsm4(uint32_t r[4], uint32_t addr) {
    asm volatile("ldmatrix.sync.aligned.m8n8.x4.shared.b16 {%0,%1,%2,%3}, [%4];"
                 : "=r"(r[0]), "=r"(r[1]), "=r"(r[2]), "=r"(r[3]) : "r"(addr));
}

__device__ __forceinline__ void mma_ff(float c[4], const uint32_t a[4],
                                       uint32_t b0, uint32_t b1) {
    asm volatile(
        "mma.sync.aligned.m16n8k16.row.col.f32.f16.f16.f32 "
        "{%0,%1,%2,%3}, {%4,%5,%6,%7}, {%8,%9}, {%0,%1,%2,%3};"
        : "+f"(c[0]), "+f"(c[1]), "+f"(c[2]), "+f"(c[3])
        : "r"(a[0]), "r"(a[1]), "r"(a[2]), "r"(a[3]), "r"(b0), "r"(b1));
}

__device__ __forceinline__ uint32_t packh2(float f0, float f1) {
    __half2 hh = __floats2half2_rn(f0, f1);
    return *(uint32_t*)&hh;
}

#define CP16(dst, src) \
    asm volatile("cp.async.cg.shared.global [%0], [%1], 16;" \
                 :: "r"(dst), "l"(src) : "memory")
#define CP_COMMIT() asm volatile("cp.async.commit_group;" ::: "memory")
#define CP_WAIT(n)  asm volatile("cp.async.wait_group %0;" :: "n"(n) : "memory")

// ---------------------------------------------------------------------------
// Kernel 1: merged qkv, single fp16 MMA. Grid 128, 512 thr = 16 warps
// (4 m x 4 n). Tile 128 x 192, K chunks of 32. Register-prefetch pipelining.
// smem: X [128 x 80B] = 10240 | W [192 x 80B] = 15360; total 25600
// ---------------------------------------------------------------------------
__global__ __launch_bounds__(512) void qkv_kernel(const float* __restrict__ x,
                                                  const float* __restrict__ Wq,
                                                  const float* __restrict__ Wk,
                                                  const float* __restrict__ Wv) {
    extern __shared__ __align__(16) char ds[];
    const uint32_t xb = smem_u32(ds);
    const uint32_t wb = xb + 10240;

    const int tid = threadIdx.x, wid = tid >> 5, lane = tid & 31;
    const int wm = wid >> 2, wn = wid & 3;
    const int m0 = blockIdx.x * 128;

    float4 px[2], pw[3];
    #pragma unroll
    for (int it = 0; it < 2; it++) {
        int i = tid + it * 512, r = i >> 3, f4 = i & 7;
        px[it] = *(const float4*)&x[(size_t)(m0 + r) * CC + f4 * 4];
    }
    #pragma unroll
    for (int it = 0; it < 3; it++) {
        int i = tid + it * 512, r = i >> 3, f4 = i & 7;
        const float* Wp = (r < 64) ? Wq : (r < 128) ? Wk : Wv;
        pw[it] = *(const float4*)&Wp[(size_t)(r & 63) * CC + f4 * 4];
    }

    float acc[2][6][4] = {};

    for (int c0 = 0; c0 < CC; c0 += 32) {
        #pragma unroll
        for (int it = 0; it < 2; it++) {
            int i = tid + it * 512, r = i >> 3, f4 = i & 7;
            uint32_t o = (uint32_t)r * 80 + f4 * 8;
            *(uint32_t*)(ds + o)     = packh2(px[it].x, px[it].y);
            *(uint32_t*)(ds + o + 4) = packh2(px[it].z, px[it].w);
        }
        #pragma unroll
        for (int it = 0; it < 3; it++) {
            int i = tid + it * 512, r = i >> 3, f4 = i & 7;
            uint32_t o = 10240 + (uint32_t)r * 80 + f4 * 8;
            *(uint32_t*)(ds + o)     = packh2(pw[it].x, pw[it].y);
            *(uint32_t*)(ds + o + 4) = packh2(pw[it].z, pw[it].w);
        }
        __syncthreads();

        if (c0 + 32 < CC) {
            const int cn = c0 + 32;
            #pragma unroll
            for (int it = 0; it < 2; it++) {
                int i = tid + it * 512, r = i >> 3, f4 = i & 7;
                px[it] = *(const float4*)&x[(size_t)(m0 + r) * CC + cn + f4 * 4];
            }
            #pragma unroll
            for (int it = 0; it < 3; it++) {
                int i = tid + it * 512, r = i >> 3, f4 = i & 7;
                const float* Wp = (r < 64) ? Wq : (r < 128) ? Wk : Wv;
                pw[it] = *(const float4*)&Wp[(size_t)(r & 63) * CC + cn + f4 * 4];
            }
        }

        #pragma unroll
        for (int j = 0; j < 2; j++) {
            uint32_t af[2][4];
            #pragma unroll
            for (int mt = 0; mt < 2; mt++) {
                uint32_t ro = (uint32_t)(wm * 32 + mt * 16 + (lane & 15)) * 80
                            + j * 32 + (lane >> 4) * 16;
                ldsm4(af[mt], xb + ro);
            }
            uint32_t bf[3][4];
            #pragma unroll
            for (int n16 = 0; n16 < 3; n16++) {
                uint32_t ro = (uint32_t)(wn * 48 + n16 * 16 + (lane & 7)
                            + ((lane >> 4) & 1) * 8) * 80
                            + ((lane >> 3) & 1) * 16 + j * 32;
                ldsm4(bf[n16], wb + ro);
            }
            #pragma unroll
            for (int mt = 0; mt < 2; mt++)
                #pragma unroll
                for (int nt = 0; nt < 6; nt++) {
                    int n16 = nt >> 1, o = (nt & 1) * 2;
                    mma_ff(acc[mt][nt], af[mt], bf[n16][o], bf[n16][o + 1]);
                }
        }
        __syncthreads();
    }

    #pragma unroll
    for (int mt = 0; mt < 2; mt++)
        #pragma unroll
        for (int nt = 0; nt < 6; nt++) {
            int row0 = m0 + wm * 32 + mt * 16 + (lane >> 2);
            int cc = wn * 48 + nt * 8 + (lane & 3) * 2;
            if (cc < 128) {
                uint32_t* gf = (uint32_t*)((cc < 64) ? g_qf : g_kf);
                int col = cc & 63;
                gf[(size_t)row0 * 32 + (col >> 1)] =
                    packh2(acc[mt][nt][0], acc[mt][nt][1]);
                gf[(size_t)(row0 + 8) * 32 + (col >> 1)] =
                    packh2(acc[mt][nt][2], acc[mt][nt][3]);
            } else {
                int col = cc - 128;
                *(float2*)&g_v[(size_t)row0 * HH + col] =
                    make_float2(acc[mt][nt][0], acc[mt][nt][1]);
                *(float2*)&g_v[(size_t)(row0 + 8) * HH + col] =
                    make_float2(acc[mt][nt][2], acc[mt][nt][3]);
            }
        }
}

// ---------------------------------------------------------------------------
// Kernel 2: zsum — fp16 scores (1 MMA) + exp + per-tile column partial sums.
// Grid (16 tt, 16 st, 8 b) lower-tri. 256 thr = 8 warps (4 m x 2 n64).
// smem: QF 0 (128x144B) | KF 18432 | zsm 36864 (512 f32) = 38912
// ---------------------------------------------------------------------------
__global__ __launch_bounds__(256) void zsum_kernel() {
    const int tt = blockIdx.x, st = blockIdx.y, b = blockIdx.z;
    if (st > tt) return;
    extern __shared__ __align__(16) char ds[];
    const uint32_t qf_b = smem_u32(ds);
    const uint32_t kf_b = qf_b + 18432;
    const int tid = threadIdx.x, wid = tid >> 5, lane = tid & 31;
    const int wm = wid >> 1, wn = wid & 1;
    const int t0 = tt * 128, s0 = st * 128;

    const uint32_t* qfg = (const uint32_t*)g_qf + ((size_t)b * TT + t0) * 32;
    const uint32_t* kfg = (const uint32_t*)g_kf + ((size_t)b * TT + s0) * 32;
    #pragma unroll
    for (int it = 0; it < 4; it++) {
        int i = tid + it * 256;
        int r = i >> 3, cg = i & 7;
        uint32_t o = (uint32_t)r * 144 + cg * 16;
        *(uint4*)(ds + o)         = *(const uint4*)(qfg + r * 32 + cg * 4);
        *(uint4*)(ds + 18432 + o) = *(const uint4*)(kfg + r * 32 + cg * 4);
    }
    __syncthreads();

    float acc[2][8][4] = {};
    #pragma unroll
    for (int j = 0; j < 4; j++) {
        uint32_t af[2][4];
        #pragma unroll
        for (int mt = 0; mt < 2; mt++) {
            uint32_t ro = (uint32_t)(wm * 32 + mt * 16 + (lane & 15)) * 144
                        + j * 32 + (lane >> 4) * 16;
            ldsm4(af[mt], qf_b + ro);
        }
        uint32_t bf[4][4];
        #pragma unroll
        for (int n16 = 0; n16 < 4; n16++) {
            uint32_t ro = (uint32_t)(wn * 64 + n16 * 16 + (lane & 7)
                        + ((lane >> 4) & 1) * 8) * 144
                        + ((lane >> 3) & 1) * 16 + j * 32;
            ldsm4(bf[n16], kf_b + ro);
        }
        #pragma unroll
        for (int mt = 0; mt < 2; mt++)
            #pragma unroll
            for (int nt = 0; nt < 8; nt++) {
                int n16 = nt >> 1, o = (nt & 1) * 2;
                mma_ff(acc[mt][nt], af[mt], bf[n16][o], bf[n16][o + 1]);
            }
    }

    // column partials: exp + mask, reduce over the warp's 32 rows via shuffles
    float* zsm = (float*)(ds + 36864);
    #pragma unroll
    for (int nt = 0; nt < 8; nt++) {
        float z0 = 0.f, z1 = 0.f;
        #pragma unroll
        for (int mt = 0; mt < 2; mt++) {
            int rA = t0 + wm * 32 + mt * 16 + (lane >> 2);
            int sc = s0 + wn * 64 + nt * 8 + (lane & 3) * 2;
            z0 += (sc <= rA)     ? __expf(acc[mt][nt][0] * SCALE) : 0.f;
            z0 += (sc <= rA + 8) ? __expf(acc[mt][nt][2] * SCALE) : 0.f;
            z1 += (sc + 1 <= rA)     ? __expf(acc[mt][nt][1] * SCALE) : 0.f;
            z1 += (sc + 1 <= rA + 8) ? __expf(acc[mt][nt][3] * SCALE) : 0.f;
        }
        z0 += __shfl_down_sync(0xffffffff, z0, 16);
        z0 += __shfl_down_sync(0xffffffff, z0, 8);
        z0 += __shfl_down_sync(0xffffffff, z0, 4);
        z1 += __shfl_down_sync(0xffffffff, z1, 16);
        z1 += __shfl_down_sync(0xffffffff, z1, 8);
        z1 += __shfl_down_sync(0xffffffff, z1, 4);
        if (lane < 4) {
            int col = wn * 64 + nt * 8 + lane * 2;
            zsm[wm * 128 + col]     = z0;
            zsm[wm * 128 + col + 1] = z1;
        }
    }
    __syncthreads();
    if (tid < 128) {
        float z = zsm[tid] + zsm[128 + tid] + zsm[256 + tid] + zsm[384 + tid];
        g_Zpart[((size_t)b * 16 + tt) * TT + s0 + tid] = z;
    }
}

// ---------------------------------------------------------------------------
// Kernel 3: Z_s, then v'[s] = v[s]/Z_s written transposed fp16 [b][h][s].
// ---------------------------------------------------------------------------
__global__ __launch_bounds__(128) void colsum_kernel() {
    const int b = blockIdx.y;
    const int s = blockIdx.x * 128 + threadIdx.x;
    float z = 0.f;
    for (int tt = s >> 7; tt < 16; tt++)
        z += g_Zpart[((size_t)b * 16 + tt) * TT + s];
    const float inv = 1.0f / z;
    const float* vp = g_v + ((size_t)b * TT + s) * HH;
    __half* tf = g_vTf + (size_t)b * HH * TT + s;
    #pragma unroll
    for (int h4 = 0; h4 < HH; h4 += 4) {
        float4 vv = *(const float4*)&vp[h4];
        tf[(size_t)(h4 + 0) * TT] = __float2half_rn(vv.x * inv);
        tf[(size_t)(h4 + 1) * TT] = __float2half_rn(vv.y * inv);
        tf[(size_t)(h4 + 2) * TT] = __float2half_rn(vv.z * inv);
        tf[(size_t)(h4 + 3) * TT] = __float2half_rn(vv.w * inv);
    }
}

// ---------------------------------------------------------------------------
// Kernel 4: fused out, tile-paired, 512 threads = 16 warps (8 wm x 2 wn).
// Each warp owns a 16-row strip -> half the accumulator registers of R14.
// Grid (8 pair, 2 split, 8 b) = 128 CTAs; CTA pp handles tt = pp and 15-pp.
// 2-stage cp.async pipeline; atomicAdd x2 per element (deterministic).
// smem: QF 0 (18432) | stage0 18432 | stage1 36864; total 55296
// ---------------------------------------------------------------------------
__global__ __launch_bounds__(512) void out_kernel(float* __restrict__ outp) {
    const int pp = blockIdx.x, split = blockIdx.y, b = blockIdx.z;
    extern __shared__ __align__(16) char ds[];
    const uint32_t sb = smem_u32(ds);
    const int tid = threadIdx.x, wid = tid >> 5, lane = tid & 31;
    const int wm = wid >> 1, wn = wid & 1;

    const uint32_t* kfg = (const uint32_t*)g_kf + (size_t)b * TT * 32;
    const uint32_t* vfg = (const uint32_t*)g_vTf + (size_t)b * HH * 1024;

    #pragma unroll 1
    for (int half = 0; half < 2; half++) {
        const int tt = half ? (15 - pp) : pp;
        const int t0 = tt * 128;
        const int nchunk = 2 * tt + 2;
        if (half) __syncthreads();            // smem reuse fence between halves

        // q tile (fp16), 128 rows x 8 cg = 1024 uint4
        const uint32_t* qfg = (const uint32_t*)g_qf + ((size_t)b * TT + t0) * 32;
        #pragma unroll
        for (int it = 0; it < 2; it++) {
            int i = tid + it * 512;
            int r = i >> 3, cg = i & 7;
            *(uint4*)(ds + (uint32_t)r * 144 + cg * 16) =
                *(const uint4*)(qfg + r * 32 + cg * 4);
        }

        auto issue = [&](int c, int buf) {
            const int s0 = c * 64;
            const uint32_t base = sb + 18432 + buf * 18432;
            int r = tid >> 3, cg = tid & 7;   // 512 thr = 64 rows x 8
            uint32_t off = (uint32_t)r * 144 + cg * 16;
            CP16(base + off,        kfg + (size_t)(s0 + r) * 32 + cg * 4);
            CP16(base + 9216 + off, vfg + (size_t)r * 1024 + (s0 >> 1) + cg * 4);
            CP_COMMIT();
        };

        float oacc[8][4] = {};
        issue(split, 0);
        int buf = 0;

        for (int c = split; c < nchunk; c += 2) {
            if (c + 2 < nchunk) { issue(c + 2, buf ^ 1); CP_WAIT(1); }
            else                { CP_WAIT(0); }
            __syncthreads();

            const uint32_t KB = sb + 18432 + buf * 18432;

            // ------ scores: warp covers 16t x 32s --------------------------
            float sacc[4][4] = {};
            #pragma unroll
            for (int j = 0; j < 4; j++) {
                uint32_t af[4];
                {
                    uint32_t ro = (uint32_t)(wm * 16 + (lane & 15)) * 144
                                + j * 32 + (lane >> 4) * 16;
                    ldsm4(af, sb + ro);
                }
                uint32_t bf[2][4];
                #pragma unroll
                for (int n16 = 0; n16 < 2; n16++) {
                    uint32_t ro = (uint32_t)(wn * 32 + n16 * 16 + (lane & 7)
                                + ((lane >> 4) & 1) * 8) * 144
                                + ((lane >> 3) & 1) * 16 + j * 32;
                    ldsm4(bf[n16], KB + ro);
                }
                #pragma unroll
                for (int blk = 0; blk < 4; blk++) {
                    int n16 = blk >> 1, o = (blk & 1) * 2;
                    mma_ff(sacc[blk], af, bf[n16][o], bf[n16][o + 1]);
                }
            }

            // ------ exp + causal mask -> P fragments (A of PV mma) ---------
            uint32_t pa[2][4];
            #pragma unroll
            for (int blk = 0; blk < 4; blk++) {
                int rA = t0 + wm * 16 + (lane >> 2);
                int sc = c * 64 + wn * 32 + blk * 8 + (lane & 3) * 2;
                float e0 = (sc     <= rA)     ? __expf(sacc[blk][0] * SCALE) : 0.f;
                float e1 = (sc + 1 <= rA)     ? __expf(sacc[blk][1] * SCALE) : 0.f;
                float e2 = (sc     <= rA + 8) ? __expf(sacc[blk][2] * SCALE) : 0.f;
                float e3 = (sc + 1 <= rA + 8) ? __expf(sacc[blk][3] * SCALE) : 0.f;
                int kk = blk >> 1;
                if ((blk & 1) == 0) {
                    pa[kk][0] = packh2(e0, e1);
                    pa[kk][1] = packh2(e2, e3);
                } else {
                    pa[kk][2] = packh2(e0, e1);
                    pa[kk][3] = packh2(e2, e3);
                }
            }

            // ------ PV: out += P (m16 x k32) @ v'^T (n64) ------------------
            #pragma unroll
            for (int kk = 0; kk < 2; kk++) {
                uint32_t bvf[4][4];
                #pragma unroll
                for (int n16 = 0; n16 < 4; n16++) {
                    uint32_t ro = (uint32_t)(n16 * 16 + (lane & 7)
                                + ((lane >> 4) & 1) * 8) * 144
                                + ((lane >> 3) & 1) * 16 + wn * 64 + kk * 32;
                    ldsm4(bvf[n16], KB + 9216 + ro);
                }
                #pragma unroll
                for (int nb = 0; nb < 8; nb++) {
                    int n16 = nb >> 1, o = (nb & 1) * 2;
                    mma_ff(oacc[nb], pa[kk], bvf[n16][o], bvf[n16][o + 1]);
                }
            }
            __syncthreads();
            buf ^= 1;
        }

        // ------ epilogue: reduce the two wn warps, then 2-way atomicAdd ----
        float* obuf = (float*)(ds + 18432);   // 128 x 68 f32 overlay
        if (wn == 0) {
            #pragma unroll
            for (int nb = 0; nb < 8; nb++) {
                int r0 = wm * 16 + (lane >> 2);
                int cc = nb * 8 + (lane & 3) * 2;
                obuf[r0 * 68 + cc]           = oacc[nb][0];
                obuf[r0 * 68 + cc + 1]       = oacc[nb][1];
                obuf[(r0 + 8) * 68 + cc]     = oacc[nb][2];
                obuf[(r0 + 8) * 68 + cc + 1] = oacc[nb][3];
            }
        }
        __syncthreads();
        if (wn == 1) {
            #pragma unroll
            for (int nb = 0; nb < 8; nb++) {
                int r0 = wm * 16 + (lane >> 2);
                int cc = nb * 8 + (lane & 3) * 2;
                obuf[r0 * 68 + cc]           += oacc[nb][0];
                obuf[r0 * 68 + cc + 1]       += oacc[nb][1];
                obuf[(r0 + 8) * 68 + cc]     += oacc[nb][2];
                obuf[(r0 + 8) * 68 + cc + 1] += oacc[nb][3];
            }
        }
        __syncthreads();
        #pragma unroll
        for (int it = 0; it < 16; it++) {
            int i = tid + it * 512;
            int r = i >> 6, cc = i & 63;
            atomicAdd(&outp[((size_t)b * TT + t0 + r) * HH + cc], obuf[r * 68 + cc]);
        }
    }
}

// ---------------------------------------------------------------------------
extern "C" void kernel_launch(void* const* d_in, const int* in_sizes, int n_in,
                              void* d_out, int out_size) {
    const float* x  = (const float*)d_in[0];
    const float* Wq = (const float*)d_in[1];
    const float* Wk = (const float*)d_in[2];
    const float* Wv = (const float*)d_in[3];
    float* out = (float*)d_out;

    cudaFuncSetAttribute(qkv_kernel,  cudaFuncAttributeMaxDynamicSharedMemorySize, 25600);
    cudaFuncSetAttribute(zsum_kernel, cudaFuncAttributeMaxDynamicSharedMemorySize, 38912);
    cudaFuncSetAttribute(out_kernel,  cudaFuncAttributeMaxDynamicSharedMemorySize, 55296);

    cudaMemsetAsync(out, 0, (size_t)out_size * sizeof(float));
    qkv_kernel<<<(BB * TT) / 128, 512, 25600>>>(x, Wq, Wk, Wv);
    zsum_kernel<<<dim3(16, 16, BB), 256, 38912>>>();
    colsum_kernel<<<dim3(16, BB), 128>>>();
    out_kernel<<<dim3(8, 2, BB), 512, 55296>>>(out);
}